// round 12
// baseline (speedup 1.0000x reference)
#include <cuda_runtime.h>
#include <cuda_bf16.h>
#include <cstdint>

#define SEQ 4096
#define HID 768
#define NH  12
#define HD  64
#define WSZ (HID * HID)
#define LOG2E 1.4426950408889634f
#define QSCALE (0.125f * LOG2E)

// ---------------- device scratch ----------------
__device__ __align__(16) __nv_bfloat16 g_xh[SEQ * HID];
__device__ __align__(16) __nv_bfloat16 g_xl[SEQ * HID];
__device__ __align__(16) __nv_bfloat16 g_wh[4 * WSZ];   // qw,kw,vw,ow
__device__ __align__(16) __nv_bfloat16 g_wl[4 * WSZ];
__device__ __align__(16) __nv_bfloat16 g_qh[NH * SEQ * HD];
__device__ __align__(16) __nv_bfloat16 g_ql[NH * SEQ * HD];
__device__ __align__(16) __nv_bfloat16 g_kh[NH * SEQ * HD];
__device__ __align__(16) __nv_bfloat16 g_kl[NH * SEQ * HD];
__device__ __align__(16) __nv_bfloat16 g_vh[NH * SEQ * HD];
__device__ __align__(16) __nv_bfloat16 g_vl[NH * SEQ * HD];
__device__ __align__(16) __nv_bfloat16 g_ch[SEQ * HID];
__device__ __align__(16) __nv_bfloat16 g_cl[SEQ * HID];

// ---------------- helpers ----------------
__device__ __forceinline__ float ex2f(float x) {
    float r;
    asm("ex2.approx.f32 %0, %1;" : "=f"(r) : "f"(x));
    return r;
}
__device__ __forceinline__ uint32_t packhi2(float a, float b) {
    uint32_t d;
    asm("prmt.b32 %0, %1, %2, 0x7632;"
        : "=r"(d) : "r"(__float_as_uint(a)), "r"(__float_as_uint(b)));
    return d;
}
__device__ __forceinline__ float truncbf(float f) {
    return __uint_as_float(__float_as_uint(f) & 0xffff0000u);
}
__device__ __forceinline__ uint32_t packlo2(float a, float b) {
    uint32_t d;
    asm("cvt.rn.bf16x2.f32 %0, %2, %1;" : "=r"(d) : "f"(a), "f"(b));
    return d;
}
__device__ __forceinline__ uint32_t smem_u32(const void* p) {
    uint32_t a;
    asm("{ .reg .u64 t; cvta.to.shared.u64 t, %1; cvt.u32.u64 %0, t; }"
        : "=r"(a) : "l"(p));
    return a;
}
__device__ __forceinline__ void ldsm4(uint32_t r[4], uint32_t addr) {
    asm volatile("ldmatrix.sync.aligned.m8n8.x4.shared.b16 {%0,%1,%2,%3}, [%4];"
                 : "=r"(r[0]), "=r"(r[1]), "=r"(r[2]), "=r"(r[3]) : "r"(addr));
}
__device__ __forceinline__ void ldsm4t(uint32_t r[4], uint32_t addr) {
    asm volatile("ldmatrix.sync.aligned.m8n8.x4.trans.shared.b16 {%0,%1,%2,%3}, [%4];"
                 : "=r"(r[0]), "=r"(r[1]), "=r"(r[2]), "=r"(r[3]) : "r"(addr));
}
__device__ __forceinline__ void mma_bf16(float d[4], const uint32_t a[4],
                                         const uint32_t b[2]) {
    asm volatile(
        "mma.sync.aligned.m16n8k16.row.col.f32.bf16.bf16.f32 "
        "{%0,%1,%2,%3}, {%4,%5,%6,%7}, {%8,%9}, {%0,%1,%2,%3};"
        : "+f"(d[0]), "+f"(d[1]), "+f"(d[2]), "+f"(d[3])
        : "r"(a[0]), "r"(a[1]), "r"(a[2]), "r"(a[3]), "r"(b[0]), "r"(b[1]));
}
__device__ __forceinline__ void cp16(uint32_t dst, const void* src) {
    asm volatile("cp.async.cg.shared.global [%0], [%1], 16;"
                 :: "r"(dst), "l"(src) : "memory");
}
#define CP_COMMIT() asm volatile("cp.async.commit_group;" ::: "memory")
template <int N>
__device__ __forceinline__ void cp_wait() {
    asm volatile("cp.async.wait_group %0;" :: "n"(N) : "memory");
}

// =====================================================================
//      split kernel: fp32 -> bf16 hi/lo (truncation split)
// =====================================================================
__global__ void __launch_bounds__(256) split_kernel(
    const float* __restrict__ X,
    const float* __restrict__ qw, const float* __restrict__ kw,
    const float* __restrict__ vw, const float* __restrict__ ow) {
    const int y = blockIdx.y;
    const float* src;
    __nv_bfloat16 *dh, *dl;
    int n;
    if (y == 0)      { src = X;  dh = g_xh;           dl = g_xl;           n = SEQ * HID; }
    else if (y == 1) { src = qw; dh = g_wh;           dl = g_wl;           n = WSZ; }
    else if (y == 2) { src = kw; dh = g_wh + WSZ;     dl = g_wl + WSZ;     n = WSZ; }
    else if (y == 3) { src = vw; dh = g_wh + 2 * WSZ; dl = g_wl + 2 * WSZ; n = WSZ; }
    else             { src = ow; dh = g_wh + 3 * WSZ; dl = g_wl + 3 * WSZ; n = WSZ; }

    int i = (blockIdx.x * 256 + threadIdx.x) * 4;
    if (i < n) {
        float4 v = *(const float4*)(src + i);
        *(uint2*)&dh[i] = make_uint2(packhi2(v.x, v.y), packhi2(v.z, v.w));
        *(uint2*)&dl[i] = make_uint2(
            packlo2(v.x - truncbf(v.x), v.y - truncbf(v.y)),
            packlo2(v.z - truncbf(v.z), v.w - truncbf(v.w)));
    }
}

// =====================================================================
//   tensor-core GEMM core: C(128x64) = A(M,768) * B(N,768)^T
//   bf16 hi/lo 3-term, KC=32, 2-stage cp.async, 3 CTAs/SM  (unchanged)
// =====================================================================
#define GK HID
#define NCHUNK (GK / 32)        // 24
#define GST 80                  // smem row stride bytes (32 bf16 data + pad)
#define GA_LO 10240
#define GB_HI 20480
#define GB_LO 25600
#define G_STG 30720
#define G_SMEM (2 * G_STG)      // 61440 -> 3 CTAs/SM

__device__ __forceinline__ void tgemm_core(
    const __nv_bfloat16* __restrict__ Ah, const __nv_bfloat16* __restrict__ Al,
    const __nv_bfloat16* __restrict__ Bh, const __nv_bfloat16* __restrict__ Bl,
    int rowBase, int colBase, uint32_t smb, float acc[2][4][4]) {
    const int tid = threadIdx.x;
    const int wid = tid >> 5, lane = tid & 31;
    const int mBase = (wid & 3) * 32, nBase = (wid >> 2) * 32;
    const int sel = lane >> 3, l7 = lane & 7;
    const int kKey = ((sel & 2) ? 8 : 0) + l7;
    const int kD = (sel & 1) ? 8 : 0;

    const int ar = tid >> 1, ac = tid & 1;
    const int br = tid >> 2, bc = tid & 3;
    const uint32_t aDst = (uint32_t)(ar * GST + ac * 32);
    const uint32_t bDst = (uint32_t)(GB_HI + br * GST + bc * 16);
    const size_t aOff = (size_t)(rowBase + ar) * GK + ac * 16;
    const size_t bOff = (size_t)(colBase + br) * GK + bc * 8;

    auto issue_chunk = [&](int kc, int stg) {
        uint32_t s = smb + stg * G_STG;
        size_t ka = aOff + (size_t)kc * 32;
        size_t kb = bOff + (size_t)kc * 32;
        cp16(s + aDst,              Ah + ka);
        cp16(s + aDst + 16,         Ah + ka + 8);
        cp16(s + aDst + GA_LO,      Al + ka);
        cp16(s + aDst + GA_LO + 16, Al + ka + 8);
        cp16(s + bDst,              Bh + kb);
        cp16(s + bDst + (GB_LO - GB_HI), Bl + kb);
        CP_COMMIT();
    };

    issue_chunk(0, 0);

    for (int kc = 0; kc < NCHUNK; kc++) {
        __syncthreads();
        if (kc + 1 < NCHUNK) issue_chunk(kc + 1, (kc + 1) & 1);
        if (kc + 1 < NCHUNK) cp_wait<1>(); else cp_wait<0>();
        __syncthreads();

        const uint32_t base = smb + (kc & 1) * G_STG;
        #pragma unroll
        for (int k2 = 0; k2 < 2; k2++) {
            const uint32_t colb = (uint32_t)(k2 * 32 + kD * 2);
            uint32_t ah[2][4], alw[2][4], bh[2][4], bl[2][4];
            #pragma unroll
            for (int mt = 0; mt < 2; mt++) {
                uint32_t addr = base + (uint32_t)((mBase + mt * 16 + kKey) * GST) + colb;
                uint32_t t[4];
                ldsm4(t, addr);
                ah[mt][0] = t[0]; ah[mt][1] = t[2]; ah[mt][2] = t[1]; ah[mt][3] = t[3];
                ldsm4(t, addr + GA_LO);
                alw[mt][0] = t[0]; alw[mt][1] = t[2]; alw[mt][2] = t[1]; alw[mt][3] = t[3];
            }
            #pragma unroll
            for (int np = 0; np < 2; np++) {
                uint32_t addr = base + GB_HI +
                                (uint32_t)((nBase + np * 16 + kKey) * GST) + colb;
                ldsm4(bh[np], addr);
                ldsm4(bl[np], addr + (GB_LO - GB_HI));
            }
            #pragma unroll
            for (int mt = 0; mt < 2; mt++)
                #pragma unroll
                for (int np = 0; np < 2; np++)
                    #pragma unroll
                    for (int h = 0; h < 2; h++) {
                        int nt = np * 2 + h;
                        mma_bf16(acc[mt][nt], ah[mt],  &bh[np][2 * h]);
                        mma_bf16(acc[mt][nt], ah[mt],  &bl[np][2 * h]);
                        mma_bf16(acc[mt][nt], alw[mt], &bh[np][2 * h]);
                    }
        }
    }
}

// ---------------- QKV: X * W^T + b, head-major bf16 hi/lo out ----------
__global__ void __launch_bounds__(256, 3) qkv_tc_kernel(
    const float* __restrict__ qb, const float* __restrict__ kb,
    const float* __restrict__ vb) {
    extern __shared__ char sm[];
    const uint32_t smb = smem_u32(sm);
    const int z = blockIdx.z;
    const __nv_bfloat16* Bh = g_wh + (size_t)z * WSZ;
    const __nv_bfloat16* Bl = g_wl + (size_t)z * WSZ;
    const float* bias = (z == 0) ? qb : (z == 1) ? kb : vb;
    __nv_bfloat16* outh = (z == 0) ? g_qh : (z == 1) ? g_kh : g_vh;
    __nv_bfloat16* outl = (z == 0) ? g_ql : (z == 1) ? g_kl : g_vl;
    const float sc = (z == 0) ? QSCALE : 1.0f;

    const int rowBase = blockIdx.y * 128, colBase = blockIdx.x * 64;

    float acc[2][4][4];
    #pragma unroll
    for (int a = 0; a < 2; a++)
        #pragma unroll
        for (int b = 0; b < 4; b++)
            #pragma unroll
            for (int c = 0; c < 4; c++) acc[a][b][c] = 0.0f;

    tgemm_core(g_xh, g_xl, Bh, Bl, rowBase, colBase, smb, acc);

    const int tid = threadIdx.x, wid = tid >> 5, lane = tid & 31;
    const int g = lane >> 2, tig = lane & 3;
    const int mBase = (wid & 3) * 32, nBase = (wid >> 2) * 32;
    const int h = colBase >> 6;

    #pragma unroll
    for (int mt = 0; mt < 2; mt++) {
        int m0 = rowBase + mBase + mt * 16 + g;
        #pragma unroll
        for (int nt = 0; nt < 4; nt++) {
            int col = colBase + nBase + nt * 8 + 2 * tig;
            int d = col & 63;
            float b0 = bias[col], b1 = bias[col + 1];
            size_t i0 = (size_t)(h * SEQ + m0) * HD + d;
            float f0 = (acc[mt][nt][0] + b0) * sc;
            float f1 = (acc[mt][nt][1] + b1) * sc;
            *(uint32_t*)&outh[i0] = packhi2(f0, f1);
            *(uint32_t*)&outl[i0] = packlo2(f0 - truncbf(f0), f1 - truncbf(f1));
            float f2 = (acc[mt][nt][2] + b0) * sc;
            float f3 = (acc[mt][nt][3] + b1) * sc;
            size_t i1 = i0 + (size_t)8 * HD;
            *(uint32_t*)&outh[i1] = packhi2(f2, f3);
            *(uint32_t*)&outl[i1] = packlo2(f2 - truncbf(f2), f3 - truncbf(f3));
        }
    }
}

// ---------------- out proj: ctx * ow^T + ob -> fp32 --------------------
__global__ void __launch_bounds__(256, 3) proj_tc_kernel(
    const float* __restrict__ ob, float* __restrict__ outp) {
    extern __shared__ char sm[];
    const uint32_t smb = smem_u32(sm);
    const int rowBase = blockIdx.y * 128, colBase = blockIdx.x * 64;

    float acc[2][4][4];
    #pragma unroll
    for (int a = 0; a < 2; a++)
        #pragma unroll
        for (int b = 0; b < 4; b++)
            #pragma unroll
            for (int c = 0; c < 4; c++) acc[a][b][c] = 0.0f;

    tgemm_core(g_ch, g_cl, g_wh + 3 * (size_t)WSZ, g_wl + 3 * (size_t)WSZ,
               rowBase, colBase, smb, acc);

    const int tid = threadIdx.x, wid = tid >> 5, lane = tid & 31;
    const int g = lane >> 2, tig = lane & 3;
    const int mBase = (wid & 3) * 32, nBase = (wid >> 2) * 32;

    #pragma unroll
    for (int mt = 0; mt < 2; mt++) {
        int m0 = rowBase + mBase + mt * 16 + g;
        #pragma unroll
        for (int nt = 0; nt < 4; nt++) {
            int col = colBase + nBase + nt * 8 + 2 * tig;
            float b0 = ob[col], b1 = ob[col + 1];
            *(float2*)&outp[(size_t)m0 * HID + col] =
                make_float2(acc[mt][nt][0] + b0, acc[mt][nt][1] + b1);
            *(float2*)&outp[(size_t)(m0 + 8) * HID + col] =
                make_float2(acc[mt][nt][2] + b0, acc[mt][nt][3] + b1);
        }
    }
}

// =====================================================================
//   flash attention: mma.sync bf16 hi/lo 3-term, 3-stage cp.async ring,
//   ONE barrier per tile, 2 CTAs/SM, MUFU ex2 softmax.
//   Q-hi in regs; Q-lo reloaded per tile from gmem (L1-hot); mask __ldg.
// =====================================================================
#define KV_STR 72
#define ARR_B  (64 * KV_STR * 2)           // 9216
#define BUF_B  (4 * ARR_B)                 // 36864 per stage
#define FL_SMEM (3 * BUF_B)                // 110592 -> 2 CTAs/SM

__global__ void __launch_bounds__(256, 2) flash_mma_kernel(const float* __restrict__ mask) {
    extern __shared__ char sm[];
    const uint32_t smb = smem_u32(sm);

    const int tid  = threadIdx.x;
    const int wid  = tid >> 5;
    const int lane = tid & 31;
    const int g    = lane >> 2;
    const int tig  = lane & 3;

    const int head  = blockIdx.y;
    const int qBase = blockIdx.x * 128;

    const int sel = lane >> 3, l7 = lane & 7;
    const int kKey = ((sel & 2) ? 8 : 0) + l7, kD = (sel & 1) ? 8 : 0;
    const int vKey = ((sel & 1) ? 8 : 0) + l7, vD = (sel & 2) ? 8 : 0;

    const int cpRow  = tid >> 2;
    const int cpChk  = tid & 3;
    const size_t gTileBase = (size_t)head * SEQ * HD;
    const uint32_t cpDstOff = (uint32_t)(cpRow * (KV_STR * 2) + cpChk * 32);

    auto issue_tile = [&](int t, int buf) {
        size_t gidx = gTileBase + (size_t)(t * 64 + cpRow) * HD + cpChk * 16;
        uint32_t d0 = smb + buf * BUF_B + cpDstOff;
        cp16(d0,                  g_kh + gidx);
        cp16(d0 + 16,             g_kh + gidx + 8);
        cp16(d0 + ARR_B,          g_kl + gidx);
        cp16(d0 + ARR_B + 16,     g_kl + gidx + 8);
        cp16(d0 + 2 * ARR_B,      g_vh + gidx);
        cp16(d0 + 2 * ARR_B + 16, g_vh + gidx + 8);
        cp16(d0 + 3 * ARR_B,      g_vl + gidx);
        cp16(d0 + 3 * ARR_B + 16, g_vl + gidx + 8);
        CP_COMMIT();
    };

    issue_tile(0, 0);
    issue_tile(1, 1);

    // ---- Q-hi fragments persistent in regs; Q-lo pointer for per-tile reload
    const uint32_t* qh32 = (const uint32_t*)g_qh + (size_t)head * SEQ * 32;
    const uint32_t* ql32 = (const uint32_t*)g_ql + (size_t)head * SEQ * 32;
    const int r0q = qBase + wid * 16 + g;
    uint32_t qfh[4][4];
    #pragma unroll
    for (int ks = 0; ks < 4; ks++) {
        int c0 = ks * 8 + tig;
        int c1 = c0 + 4;
        qfh[ks][0] = qh32[r0q * 32 + c0];
        qfh[ks][1] = qh32[(r0q + 8) * 32 + c0];
        qfh[ks][2] = qh32[r0q * 32 + c1];
        qfh[ks][3] = qh32[(r0q + 8) * 32 + c1];
    }

    float o[8][4];
    #pragma unroll
    for (int j = 0; j < 8; j++)
        #pragma unroll
        for (int r = 0; r < 4; r++) o[j][r] = 0.0f;
    float l0 = 0.0f, l1 = 0.0f;

    for (int t = 0; t < 64; t++) {
        __syncthreads();                   // all warps done with tile t-1
        if (t + 2 < 64) issue_tile(t + 2, (t + 2) % 3);  // overwrites stage of t-1
        if (t + 2 < 64)      cp_wait<2>(); // tile t landed
        else if (t + 1 < 64) cp_wait<1>();
        else                 cp_wait<0>();

        const uint32_t kb = smb + (t % 3) * BUF_B;
        const uint32_t sKhi = kb, sKlo = kb + ARR_B;
        const uint32_t sVhi = kb + 2 * ARR_B, sVlo = kb + 3 * ARR_B;

        float sacc[8][4];
        #pragma unroll
        for (int j = 0; j < 8; j++)
            #pragma unroll
            for (int r = 0; r < 4; r++) sacc[j][r] = 0.0f;

        #pragma unroll
        for (int ks = 0; ks < 4; ks++) {
            // Q-lo fragment reloaded from gmem (L1-hot, 16KB tile)
            uint32_t qlo[4];
            {
                int c0 = ks * 8 + tig;
                int c1 = c0 + 4;
                qlo[0] = __ldg(&ql32[r0q * 32 + c0]);
                qlo[1] = __ldg(&ql32[(r0q + 8) * 32 + c0]);
                qlo[2] = __ldg(&ql32[r0q * 32 + c1]);
                qlo[3] = __ldg(&ql32[(r0q + 8) * 32 + c1]);
            }
            #pragma unroll
            for (int jp = 0; jp < 4; jp++) {
                uint32_t boff = (uint32_t)(((16 * jp + kKey) * KV_STR + 16 * ks + kD) * 2);
                uint32_t kh[4], kl[4];
                ldsm4(kh, sKhi + boff);
                ldsm4(kl, sKlo + boff);
                mma_bf16(sacc[2 * jp],     qfh[ks], &kh[0]);
                mma_bf16(sacc[2 * jp],     qfh[ks], &kl[0]);
                mma_bf16(sacc[2 * jp],     qlo,     &kh[0]);
                mma_bf16(sacc[2 * jp + 1], qfh[ks], &kh[2]);
                mma_bf16(sacc[2 * jp + 1], qfh[ks], &kl[2]);
                mma_bf16(sacc[2 * jp + 1], qlo,     &kh[2]);
            }
        }

        // softmax: MUFU ex2 + truncation split packing; mask via __ldg
        uint32_t pfh[4][4], pfl[4][4];
        #pragma unroll
        for (int j = 0; j < 8; j++) {
            float2 m2 = __ldg((const float2*)&mask[t * 64 + 8 * j + 2 * tig]);
            m2.x *= LOG2E; m2.y *= LOG2E;
            float p0 = ex2f(sacc[j][0] + m2.x);
            float p1 = ex2f(sacc[j][1] + m2.y);
            float p2 = ex2f(sacc[j][2] + m2.x);
            float p3 = ex2f(sacc[j][3] + m2.y);
            l0 += p0 + p1;
            l1 += p2 + p3;
            int ks = j >> 1, odd = (j & 1) ? 2 : 0;
            pfh[ks][odd]     = packhi2(p0, p1);
            pfh[ks][odd + 1] = packhi2(p2, p3);
            pfl[ks][odd]     = packlo2(p0 - truncbf(p0), p1 - truncbf(p1));
            pfl[ks][odd + 1] = packlo2(p2 - truncbf(p2), p3 - truncbf(p3));
        }

        #pragma unroll
        for (int ks = 0; ks < 4; ks++) {
            #pragma unroll
            for (int jd = 0; jd < 4; jd++) {
                uint32_t boff = (uint32_t)(((16 * ks + vKey) * KV_STR + 16 * jd + vD) * 2);
                uint32_t vh[4], vl[4];
                ldsm4t(vh, sVhi + boff);
                ldsm4t(vl, sVlo + boff);
                mma_bf16(o[2 * jd],     pfh[ks], &vh[0]);
                mma_bf16(o[2 * jd],     pfh[ks], &vl[0]);
                mma_bf16(o[2 * jd],     pfl[ks], &vh[0]);
                mma_bf16(o[2 * jd + 1], pfh[ks], &vh[2]);
                mma_bf16(o[2 * jd + 1], pfh[ks], &vl[2]);
                mma_bf16(o[2 * jd + 1], pfl[ks], &vh[2]);
            }
        }
    }

    l0 += __shfl_xor_sync(0xffffffffu, l0, 1);
    l0 += __shfl_xor_sync(0xffffffffu, l0, 2);
    l1 += __shfl_xor_sync(0xffffffffu, l1, 1);
    l1 += __shfl_xor_sync(0xffffffffu, l1, 2);
    float inv0 = 1.0f / l0, inv1 = 1.0f / l1;

    const int r0 = qBase + wid * 16 + g;
    #pragma unroll
    for (int j = 0; j < 8; j++) {
        int c = 8 * j + 2 * tig;
        size_t i0 = (size_t)r0 * HID + head * HD + c;
        size_t i1 = (size_t)(r0 + 8) * HID + head * HD + c;
        float a0 = o[j][0] * inv0, a1 = o[j][1] * inv0;
        float a2 = o[j][2] * inv1, a3 = o[j][3] * inv1;
        *(uint32_t*)&g_ch[i0] = packhi2(a0, a1);
        *(uint32_t*)&g_cl[i0] = packlo2(a0 - truncbf(a0), a1 - truncbf(a1));
        *(uint32_t*)&g_ch[i1] = packhi2(a2, a3);
        *(uint32_t*)&g_cl[i1] = packlo2(a2 - truncbf(a2), a3 - truncbf(a3));
    }
}

// ---------------- launch ------------------------------------------------
extern "C" void kernel_launch(void* const* d_in, const int* in_sizes, int n_in,
                              void* d_out, int out_size) {
    const float* X    = (const float*)d_in[0];
    const float* mask = (const float*)d_in[1];
    const float* qw   = (const float*)d_in[2];
    const float* qb   = (const float*)d_in[3];
    const float* kw   = (const float*)d_in[4];
    const float* kb   = (const float*)d_in[5];
    const float* vw   = (const float*)d_in[6];
    const float* vb   = (const float*)d_in[7];
    const float* ow   = (const float*)d_in[8];
    const float* ob   = (const float*)d_in[9];
    float* out = (float*)d_out;

    cudaFuncSetAttribute(flash_mma_kernel,
                         cudaFuncAttributeMaxDynamicSharedMemorySize, FL_SMEM);
    cudaFuncSetAttribute(qkv_tc_kernel,
                         cudaFuncAttributeMaxDynamicSharedMemorySize, G_SMEM);
    cudaFuncSetAttribute(proj_tc_kernel,
                         cudaFuncAttributeMaxDynamicSharedMemorySize, G_SMEM);

    split_kernel<<<dim3(SEQ * HID / 1024, 5), 256>>>(X, qw, kw, vw, ow);

    qkv_tc_kernel<<<dim3(HID / 64, SEQ / 128, 3), 256, G_SMEM>>>(qb, kb, vb);

    flash_mma_kernel<<<dim3(SEQ / 128, NH), 256, FL_SMEM>>>(mask);

    proj_tc_kernel<<<dim3(HID / 64, SEQ / 128), 256, G_SMEM>>>(ob, out);
}

// round 13
// speedup vs baseline: 1.1813x; 1.1813x over previous
#include <cuda_runtime.h>
#include <cuda_bf16.h>
#include <cstdint>

#define SEQ 4096
#define HID 768
#define NH  12
#define HD  64
#define WSZ (HID * HID)
#define LOG2E 1.4426950408889634f
#define QSCALE (0.125f * LOG2E)

// ---------------- device scratch ----------------
__device__ __align__(16) __nv_bfloat16 g_xh[SEQ * HID];
__device__ __align__(16) __nv_bfloat16 g_xl[SEQ * HID];
__device__ __align__(16) __nv_bfloat16 g_wh[4 * WSZ];   // qw,kw,vw,ow
__device__ __align__(16) __nv_bfloat16 g_wl[4 * WSZ];
__device__ __align__(16) __nv_bfloat16 g_qh[NH * SEQ * HD];
__device__ __align__(16) __nv_bfloat16 g_ql[NH * SEQ * HD];
__device__ __align__(16) __nv_bfloat16 g_kh[NH * SEQ * HD];   // RN bf16 (no lo)
__device__ __align__(16) __nv_bfloat16 g_vh[NH * SEQ * HD];
__device__ __align__(16) __nv_bfloat16 g_vl[NH * SEQ * HD];
__device__ __align__(16) __nv_bfloat16 g_ch[SEQ * HID];
__device__ __align__(16) __nv_bfloat16 g_cl[SEQ * HID];

// ---------------- helpers ----------------
__device__ __forceinline__ float ex2f(float x) {
    float r;
    asm("ex2.approx.f32 %0, %1;" : "=f"(r) : "f"(x));
    return r;
}
__device__ __forceinline__ uint32_t packhi2(float a, float b) {
    uint32_t d;
    asm("prmt.b32 %0, %1, %2, 0x7632;"
        : "=r"(d) : "r"(__float_as_uint(a)), "r"(__float_as_uint(b)));
    return d;
}
__device__ __forceinline__ float truncbf(float f) {
    return __uint_as_float(__float_as_uint(f) & 0xffff0000u);
}
// RN bf16 pair: lo16 = bf16rn(a), hi16 = bf16rn(b)
__device__ __forceinline__ uint32_t packlo2(float a, float b) {
    uint32_t d;
    asm("cvt.rn.bf16x2.f32 %0, %2, %1;" : "=r"(d) : "f"(a), "f"(b));
    return d;
}
__device__ __forceinline__ uint32_t smem_u32(const void* p) {
    uint32_t a;
    asm("{ .reg .u64 t; cvta.to.shared.u64 t, %1; cvt.u32.u64 %0, t; }"
        : "=r"(a) : "l"(p));
    return a;
}
__device__ __forceinline__ void ldsm4(uint32_t r[4], uint32_t addr) {
    asm volatile("ldmatrix.sync.aligned.m8n8.x4.shared.b16 {%0,%1,%2,%3}, [%4];"
                 : "=r"(r[0]), "=r"(r[1]), "=r"(r[2]), "=r"(r[3]) : "r"(addr));
}
__device__ __forceinline__ void ldsm4t(uint32_t r[4], uint32_t addr) {
    asm volatile("ldmatrix.sync.aligned.m8n8.x4.trans.shared.b16 {%0,%1,%2,%3}, [%4];"
                 : "=r"(r[0]), "=r"(r[1]), "=r"(r[2]), "=r"(r[3]) : "r"(addr));
}
__device__ __forceinline__ void mma_bf16(float d[4], const uint32_t a[4],
                                         const uint32_t b[2]) {
    asm volatile(
        "mma.sync.aligned.m16n8k16.row.col.f32.bf16.bf16.f32 "
        "{%0,%1,%2,%3}, {%4,%5,%6,%7}, {%8,%9}, {%0,%1,%2,%3};"
        : "+f"(d[0]), "+f"(d[1]), "+f"(d[2]), "+f"(d[3])
        : "r"(a[0]), "r"(a[1]), "r"(a[2]), "r"(a[3]), "r"(b[0]), "r"(b[1]));
}
__device__ __forceinline__ void cp16(uint32_t dst, const void* src) {
    asm volatile("cp.async.cg.shared.global [%0], [%1], 16;"
                 :: "r"(dst), "l"(src) : "memory");
}
#define CP_COMMIT() asm volatile("cp.async.commit_group;" ::: "memory")
template <int N>
__device__ __forceinline__ void cp_wait() {
    asm volatile("cp.async.wait_group %0;" :: "n"(N) : "memory");
}

// =====================================================================
//      split kernel: fp32 -> bf16 hi/lo (truncation split)
// =====================================================================
__global__ void __launch_bounds__(256) split_kernel(
    const float* __restrict__ X,
    const float* __restrict__ qw, const float* __restrict__ kw,
    const float* __restrict__ vw, const float* __restrict__ ow) {
    const int y = blockIdx.y;
    const float* src;
    __nv_bfloat16 *dh, *dl;
    int n;
    if (y == 0)      { src = X;  dh = g_xh;           dl = g_xl;           n = SEQ * HID; }
    else if (y == 1) { src = qw; dh = g_wh;           dl = g_wl;           n = WSZ; }
    else if (y == 2) { src = kw; dh = g_wh + WSZ;     dl = g_wl + WSZ;     n = WSZ; }
    else if (y == 3) { src = vw; dh = g_wh + 2 * WSZ; dl = g_wl + 2 * WSZ; n = WSZ; }
    else             { src = ow; dh = g_wh + 3 * WSZ; dl = g_wl + 3 * WSZ; n = WSZ; }

    int i = (blockIdx.x * 256 + threadIdx.x) * 4;
    if (i < n) {
        float4 v = *(const float4*)(src + i);
        *(uint2*)&dh[i] = make_uint2(packhi2(v.x, v.y), packhi2(v.z, v.w));
        *(uint2*)&dl[i] = make_uint2(
            packlo2(v.x - truncbf(v.x), v.y - truncbf(v.y)),
            packlo2(v.z - truncbf(v.z), v.w - truncbf(v.w)));
    }
}

// =====================================================================
//   tensor-core GEMM core: C(128x64) = A(M,768) * B(N,768)^T
//   bf16 hi/lo 3-term, KC=32, 2-stage cp.async, 3 CTAs/SM  (unchanged)
// =====================================================================
#define GK HID
#define NCHUNK (GK / 32)        // 24
#define GST 80
#define GA_LO 10240
#define GB_HI 20480
#define GB_LO 25600
#define G_STG 30720
#define G_SMEM (2 * G_STG)      // 61440 -> 3 CTAs/SM

__device__ __forceinline__ void tgemm_core(
    const __nv_bfloat16* __restrict__ Ah, const __nv_bfloat16* __restrict__ Al,
    const __nv_bfloat16* __restrict__ Bh, const __nv_bfloat16* __restrict__ Bl,
    int rowBase, int colBase, uint32_t smb, float acc[2][4][4]) {
    const int tid = threadIdx.x;
    const int wid = tid >> 5, lane = tid & 31;
    const int mBase = (wid & 3) * 32, nBase = (wid >> 2) * 32;
    const int sel = lane >> 3, l7 = lane & 7;
    const int kKey = ((sel & 2) ? 8 : 0) + l7;
    const int kD = (sel & 1) ? 8 : 0;

    const int ar = tid >> 1, ac = tid & 1;
    const int br = tid >> 2, bc = tid & 3;
    const uint32_t aDst = (uint32_t)(ar * GST + ac * 32);
    const uint32_t bDst = (uint32_t)(GB_HI + br * GST + bc * 16);
    const size_t aOff = (size_t)(rowBase + ar) * GK + ac * 16;
    const size_t bOff = (size_t)(colBase + br) * GK + bc * 8;

    auto issue_chunk = [&](int kc, int stg) {
        uint32_t s = smb + stg * G_STG;
        size_t ka = aOff + (size_t)kc * 32;
        size_t kb = bOff + (size_t)kc * 32;
        cp16(s + aDst,              Ah + ka);
        cp16(s + aDst + 16,         Ah + ka + 8);
        cp16(s + aDst + GA_LO,      Al + ka);
        cp16(s + aDst + GA_LO + 16, Al + ka + 8);
        cp16(s + bDst,              Bh + kb);
        cp16(s + bDst + (GB_LO - GB_HI), Bl + kb);
        CP_COMMIT();
    };

    issue_chunk(0, 0);

    for (int kc = 0; kc < NCHUNK; kc++) {
        __syncthreads();
        if (kc + 1 < NCHUNK) issue_chunk(kc + 1, (kc + 1) & 1);
        if (kc + 1 < NCHUNK) cp_wait<1>(); else cp_wait<0>();
        __syncthreads();

        const uint32_t base = smb + (kc & 1) * G_STG;
        #pragma unroll
        for (int k2 = 0; k2 < 2; k2++) {
            const uint32_t colb = (uint32_t)(k2 * 32 + kD * 2);
            uint32_t ah[2][4], alw[2][4], bh[2][4], bl[2][4];
            #pragma unroll
            for (int mt = 0; mt < 2; mt++) {
                uint32_t addr = base + (uint32_t)((mBase + mt * 16 + kKey) * GST) + colb;
                uint32_t t[4];
                ldsm4(t, addr);
                ah[mt][0] = t[0]; ah[mt][1] = t[2]; ah[mt][2] = t[1]; ah[mt][3] = t[3];
                ldsm4(t, addr + GA_LO);
                alw[mt][0] = t[0]; alw[mt][1] = t[2]; alw[mt][2] = t[1]; alw[mt][3] = t[3];
            }
            #pragma unroll
            for (int np = 0; np < 2; np++) {
                uint32_t addr = base + GB_HI +
                                (uint32_t)((nBase + np * 16 + kKey) * GST) + colb;
                ldsm4(bh[np], addr);
                ldsm4(bl[np], addr + (GB_LO - GB_HI));
            }
            #pragma unroll
            for (int mt = 0; mt < 2; mt++)
                #pragma unroll
                for (int np = 0; np < 2; np++)
                    #pragma unroll
                    for (int h = 0; h < 2; h++) {
                        int nt = np * 2 + h;
                        mma_bf16(acc[mt][nt], ah[mt],  &bh[np][2 * h]);
                        mma_bf16(acc[mt][nt], ah[mt],  &bl[np][2 * h]);
                        mma_bf16(acc[mt][nt], alw[mt], &bh[np][2 * h]);
                    }
        }
    }
}

// ---------------- QKV: X * W^T + b, head-major bf16 out ----------------
// z==0 (Q): hi=trunc + lo residual; z==1 (K): single RN bf16; z==2 (V): hi+lo
__global__ void __launch_bounds__(256, 3) qkv_tc_kernel(
    const float* __restrict__ qb, const float* __restrict__ kb,
    const float* __restrict__ vb) {
    extern __shared__ char sm[];
    const uint32_t smb = smem_u32(sm);
    const int z = blockIdx.z;
    const __nv_bfloat16* Bh = g_wh + (size_t)z * WSZ;
    const __nv_bfloat16* Bl = g_wl + (size_t)z * WSZ;
    const float* bias = (z == 0) ? qb : (z == 1) ? kb : vb;
    __nv_bfloat16* outh = (z == 0) ? g_qh : (z == 1) ? g_kh : g_vh;
    __nv_bfloat16* outl = (z == 0) ? g_ql : g_vl;   // unused for z==1
    const float sc = (z == 0) ? QSCALE : 1.0f;

    const int rowBase = blockIdx.y * 128, colBase = blockIdx.x * 64;

    float acc[2][4][4];
    #pragma unroll
    for (int a = 0; a < 2; a++)
        #pragma unroll
        for (int b = 0; b < 4; b++)
            #pragma unroll
            for (int c = 0; c < 4; c++) acc[a][b][c] = 0.0f;

    tgemm_core(g_xh, g_xl, Bh, Bl, rowBase, colBase, smb, acc);

    const int tid = threadIdx.x, wid = tid >> 5, lane = tid & 31;
    const int g = lane >> 2, tig = lane & 3;
    const int mBase = (wid & 3) * 32, nBase = (wid >> 2) * 32;
    const int h = colBase >> 6;

    #pragma unroll
    for (int mt = 0; mt < 2; mt++) {
        int m0 = rowBase + mBase + mt * 16 + g;
        #pragma unroll
        for (int nt = 0; nt < 4; nt++) {
            int col = colBase + nBase + nt * 8 + 2 * tig;
            int d = col & 63;
            float b0 = bias[col], b1 = bias[col + 1];
            size_t i0 = (size_t)(h * SEQ + m0) * HD + d;
            size_t i1 = i0 + (size_t)8 * HD;
            float f0 = (acc[mt][nt][0] + b0) * sc;
            float f1 = (acc[mt][nt][1] + b1) * sc;
            float f2 = (acc[mt][nt][2] + b0) * sc;
            float f3 = (acc[mt][nt][3] + b1) * sc;
            if (z == 1) {
                // K: single RN bf16 (unbiased; no lo term needed in S)
                *(uint32_t*)&outh[i0] = packlo2(f0, f1);
                *(uint32_t*)&outh[i1] = packlo2(f2, f3);
            } else {
                *(uint32_t*)&outh[i0] = packhi2(f0, f1);
                *(uint32_t*)&outl[i0] = packlo2(f0 - truncbf(f0), f1 - truncbf(f1));
                *(uint32_t*)&outh[i1] = packhi2(f2, f3);
                *(uint32_t*)&outl[i1] = packlo2(f2 - truncbf(f2), f3 - truncbf(f3));
            }
        }
    }
}

// ---------------- out proj: ctx * ow^T + ob -> fp32 --------------------
__global__ void __launch_bounds__(256, 3) proj_tc_kernel(
    const float* __restrict__ ob, float* __restrict__ outp) {
    extern __shared__ char sm[];
    const uint32_t smb = smem_u32(sm);
    const int rowBase = blockIdx.y * 128, colBase = blockIdx.x * 64;

    float acc[2][4][4];
    #pragma unroll
    for (int a = 0; a < 2; a++)
        #pragma unroll
        for (int b = 0; b < 4; b++)
            #pragma unroll
            for (int c = 0; c < 4; c++) acc[a][b][c] = 0.0f;

    tgemm_core(g_ch, g_cl, g_wh + 3 * (size_t)WSZ, g_wl + 3 * (size_t)WSZ,
               rowBase, colBase, smb, acc);

    const int tid = threadIdx.x, wid = tid >> 5, lane = tid & 31;
    const int g = lane >> 2, tig = lane & 3;
    const int mBase = (wid & 3) * 32, nBase = (wid >> 2) * 32;

    #pragma unroll
    for (int mt = 0; mt < 2; mt++) {
        int m0 = rowBase + mBase + mt * 16 + g;
        #pragma unroll
        for (int nt = 0; nt < 4; nt++) {
            int col = colBase + nBase + nt * 8 + 2 * tig;
            float b0 = ob[col], b1 = ob[col + 1];
            *(float2*)&outp[(size_t)m0 * HID + col] =
                make_float2(acc[mt][nt][0] + b0, acc[mt][nt][1] + b1);
            *(float2*)&outp[(size_t)(m0 + 8) * HID + col] =
                make_float2(acc[mt][nt][2] + b0, acc[mt][nt][3] + b1);
        }
    }
}

// =====================================================================
//   flash attention: round-10 structure (2-stage, Q-lo smem, mask smem),
//   S = 2-term (Qhi+Qlo)xK_rn;  PV = 3-term.  K-lo eliminated.
// =====================================================================
#define KV_STR 72
#define ARR_B  (64 * KV_STR * 2)           // 9216
#define BUF_B  (3 * ARR_B)                 // 27648 per stage (Khi,Vhi,Vlo)
#define QLO_OFF (2 * BUF_B)                // 55296
#define QLO_B  (128 * KV_STR * 2)          // 18432
#define MSK_OFF (QLO_OFF + QLO_B)          // 73728
#define FL_SMEM (MSK_OFF + SEQ * 4)        // 90112 -> 2 CTAs/SM

__global__ void __launch_bounds__(256, 2) flash_mma_kernel(const float* __restrict__ mask) {
    extern __shared__ char sm[];
    const uint32_t smb = smem_u32(sm);
    float* mskp = (float*)(sm + MSK_OFF);

    const int tid  = threadIdx.x;
    const int wid  = tid >> 5;
    const int lane = tid & 31;
    const int g    = lane >> 2;
    const int tig  = lane & 3;

    const int head  = blockIdx.y;
    const int qBase = blockIdx.x * 128;

    const int sel = lane >> 3, l7 = lane & 7;
    const int kKey = ((sel & 2) ? 8 : 0) + l7, kD = (sel & 1) ? 8 : 0;
    const int vKey = ((sel & 1) ? 8 : 0) + l7, vD = (sel & 2) ? 8 : 0;

    // ---- Q-lo tile -> smem via cp.async ----
    {
        int row = tid >> 1, half = tid & 1;
        const __nv_bfloat16* src =
            g_ql + ((size_t)head * SEQ + qBase + row) * HD + half * 32;
        uint32_t dst = smb + QLO_OFF + (uint32_t)(row * (KV_STR * 2) + half * 64);
        cp16(dst,      src);
        cp16(dst + 16, src + 8);
        cp16(dst + 32, src + 16);
        cp16(dst + 48, src + 24);
    }
    CP_COMMIT();

    const int cpRow  = tid >> 2;
    const int cpChk  = tid & 3;
    const size_t gTileBase = (size_t)head * SEQ * HD;
    const uint32_t cpDstOff = (uint32_t)(cpRow * (KV_STR * 2) + cpChk * 32);

    auto issue_tile = [&](int t, int buf) {
        size_t gidx = gTileBase + (size_t)(t * 64 + cpRow) * HD + cpChk * 16;
        uint32_t d0 = smb + buf * BUF_B + cpDstOff;
        cp16(d0,                  g_kh + gidx);
        cp16(d0 + 16,             g_kh + gidx + 8);
        cp16(d0 + ARR_B,          g_vh + gidx);
        cp16(d0 + ARR_B + 16,     g_vh + gidx + 8);
        cp16(d0 + 2 * ARR_B,      g_vl + gidx);
        cp16(d0 + 2 * ARR_B + 16, g_vl + gidx + 8);
        CP_COMMIT();
    };

    issue_tile(0, 0);

    // ---- Q-hi fragments from gmem (registers) ----
    uint32_t qfh[4][4];
    {
        const uint32_t* qh32 = (const uint32_t*)g_qh + (size_t)head * SEQ * 32;
        const int r0 = qBase + wid * 16 + g;
        #pragma unroll
        for (int ks = 0; ks < 4; ks++) {
            int c0 = ks * 8 + tig;
            int c1 = c0 + 4;
            qfh[ks][0] = qh32[r0 * 32 + c0];
            qfh[ks][1] = qh32[(r0 + 8) * 32 + c0];
            qfh[ks][2] = qh32[r0 * 32 + c1];
            qfh[ks][3] = qh32[(r0 + 8) * 32 + c1];
        }
    }

    // preload whole mask (x log2e) once
    for (int i = tid; i < SEQ / 4; i += 256) {
        float4 v = ((const float4*)mask)[i];
        v.x *= LOG2E; v.y *= LOG2E; v.z *= LOG2E; v.w *= LOG2E;
        ((float4*)mskp)[i] = v;
    }

    float o[8][4];
    #pragma unroll
    for (int j = 0; j < 8; j++)
        #pragma unroll
        for (int r = 0; r < 4; r++) o[j][r] = 0.0f;
    float l0 = 0.0f, l1 = 0.0f;

    const uint32_t qloBase = smb + QLO_OFF +
        (uint32_t)(((wid * 16 + kKey) * KV_STR + kD) * 2);

    for (int t = 0; t < 64; t++) {
        __syncthreads();                 // buf[(t+1)&1] fully consumed by t-1
        if (t + 1 < 64) issue_tile(t + 1, (t + 1) & 1);
        if (t + 1 < 64) cp_wait<1>(); else cp_wait<0>();
        __syncthreads();                 // tile t (and at t=0 qlo) visible

        const uint32_t kb = smb + (t & 1) * BUF_B;
        const uint32_t sKhi = kb;
        const uint32_t sVhi = kb + ARR_B, sVlo = kb + 2 * ARR_B;

        float sacc[8][4];
        #pragma unroll
        for (int j = 0; j < 8; j++)
            #pragma unroll
            for (int r = 0; r < 4; r++) sacc[j][r] = 0.0f;

        #pragma unroll
        for (int ks = 0; ks < 4; ks++) {
            uint32_t tq[4], qlo[4];
            ldsm4(tq, qloBase + (uint32_t)(32 * ks));
            qlo[0] = tq[0]; qlo[1] = tq[2]; qlo[2] = tq[1]; qlo[3] = tq[3];
            #pragma unroll
            for (int jp = 0; jp < 4; jp++) {
                uint32_t boff = (uint32_t)(((16 * jp + kKey) * KV_STR + 16 * ks + kD) * 2);
                uint32_t kh[4];
                ldsm4(kh, sKhi + boff);
                mma_bf16(sacc[2 * jp],     qfh[ks], &kh[0]);
                mma_bf16(sacc[2 * jp],     qlo,     &kh[0]);
                mma_bf16(sacc[2 * jp + 1], qfh[ks], &kh[2]);
                mma_bf16(sacc[2 * jp + 1], qlo,     &kh[2]);
            }
        }

        // softmax: MUFU ex2 + truncation split packing
        uint32_t pfh[4][4], pfl[4][4];
        #pragma unroll
        for (int j = 0; j < 8; j++) {
            float2 m2 = *(const float2*)&mskp[t * 64 + 8 * j + 2 * tig];
            float p0 = ex2f(sacc[j][0] + m2.x);
            float p1 = ex2f(sacc[j][1] + m2.y);
            float p2 = ex2f(sacc[j][2] + m2.x);
            float p3 = ex2f(sacc[j][3] + m2.y);
            l0 += p0 + p1;
            l1 += p2 + p3;
            int ks = j >> 1, odd = (j & 1) ? 2 : 0;
            pfh[ks][odd]     = packhi2(p0, p1);
            pfh[ks][odd + 1] = packhi2(p2, p3);
            pfl[ks][odd]     = packlo2(p0 - truncbf(p0), p1 - truncbf(p1));
            pfl[ks][odd + 1] = packlo2(p2 - truncbf(p2), p3 - truncbf(p3));
        }

        #pragma unroll
        for (int ks = 0; ks < 4; ks++) {
            #pragma unroll
            for (int jd = 0; jd < 4; jd++) {
                uint32_t boff = (uint32_t)(((16 * ks + vKey) * KV_STR + 16 * jd + vD) * 2);
                uint32_t vh[4], vl[4];
                ldsm4t(vh, sVhi + boff);
                ldsm4t(vl, sVlo + boff);
                mma_bf16(o[2 * jd],     pfh[ks], &vh[0]);
                mma_bf16(o[2 * jd],     pfh[ks], &vl[0]);
                mma_bf16(o[2 * jd],     pfl[ks], &vh[0]);
                mma_bf16(o[2 * jd + 1], pfh[ks], &vh[2]);
                mma_bf16(o[2 * jd + 1], pfh[ks], &vl[2]);
                mma_bf16(o[2 * jd + 1], pfl[ks], &vh[2]);
            }
        }
    }

    l0 += __shfl_xor_sync(0xffffffffu, l0, 1);
    l0 += __shfl_xor_sync(0xffffffffu, l0, 2);
    l1 += __shfl_xor_sync(0xffffffffu, l1, 1);
    l1 += __shfl_xor_sync(0xffffffffu, l1, 2);
    float inv0 = 1.0f / l0, inv1 = 1.0f / l1;

    const int r0 = qBase + wid * 16 + g;
    #pragma unroll
    for (int j = 0; j < 8; j++) {
        int c = 8 * j + 2 * tig;
        size_t i0 = (size_t)r0 * HID + head * HD + c;
        size_t i1 = (size_t)(r0 + 8) * HID + head * HD + c;
        float a0 = o[j][0] * inv0, a1 = o[j][1] * inv0;
        float a2 = o[j][2] * inv1, a3 = o[j][3] * inv1;
        *(uint32_t*)&g_ch[i0] = packhi2(a0, a1);
        *(uint32_t*)&g_cl[i0] = packlo2(a0 - truncbf(a0), a1 - truncbf(a1));
        *(uint32_t*)&g_ch[i1] = packhi2(a2, a3);
        *(uint32_t*)&g_cl[i1] = packlo2(a2 - truncbf(a2), a3 - truncbf(a3));
    }
}

// ---------------- launch ------------------------------------------------
extern "C" void kernel_launch(void* const* d_in, const int* in_sizes, int n_in,
                              void* d_out, int out_size) {
    const float* X    = (const float*)d_in[0];
    const float* mask = (const float*)d_in[1];
    const float* qw   = (const float*)d_in[2];
    const float* qb   = (const float*)d_in[3];
    const float* kw   = (const float*)d_in[4];
    const float* kb   = (const float*)d_in[5];
    const float* vw   = (const float*)d_in[6];
    const float* vb   = (const float*)d_in[7];
    const float* ow   = (const float*)d_in[8];
    const float* ob   = (const float*)d_in[9];
    float* out = (float*)d_out;

    cudaFuncSetAttribute(flash_mma_kernel,
                         cudaFuncAttributeMaxDynamicSharedMemorySize, FL_SMEM);
    cudaFuncSetAttribute(qkv_tc_kernel,
                         cudaFuncAttributeMaxDynamicSharedMemorySize, G_SMEM);
    cudaFuncSetAttribute(proj_tc_kernel,
                         cudaFuncAttributeMaxDynamicSharedMemorySize, G_SMEM);

    split_kernel<<<dim3(SEQ * HID / 1024, 5), 256>>>(X, qw, kw, vw, ow);

    qkv_tc_kernel<<<dim3(HID / 64, SEQ / 128, 3), 256, G_SMEM>>>(qb, kb, vb);

    flash_mma_kernel<<<dim3(SEQ / 128, NH), 256, FL_SMEM>>>(mask);

    proj_tc_kernel<<<dim3(HID / 64, SEQ / 128), 256, G_SMEM>>>(ob, out);
}

// round 14
// speedup vs baseline: 1.2140x; 1.0276x over previous
#include <cuda_runtime.h>
#include <cuda_bf16.h>
#include <cstdint>

#define SEQ 4096
#define HID 768
#define NH  12
#define HD  64
#define WSZ (HID * HID)
#define LOG2E 1.4426950408889634f
#define QSCALE (0.125f * LOG2E)

// ---------------- device scratch ----------------
__device__ __align__(16) __nv_bfloat16 g_xh[SEQ * HID];
__device__ __align__(16) __nv_bfloat16 g_xl[SEQ * HID];
__device__ __align__(16) __nv_bfloat16 g_wh[4 * WSZ];   // qw,kw,vw,ow
__device__ __align__(16) __nv_bfloat16 g_wl[4 * WSZ];
__device__ __align__(16) __nv_bfloat16 g_qh[NH * SEQ * HD];
__device__ __align__(16) __nv_bfloat16 g_ql[NH * SEQ * HD];
__device__ __align__(16) __nv_bfloat16 g_kh[NH * SEQ * HD];   // RN bf16 (no lo)
__device__ __align__(16) __nv_bfloat16 g_vh[NH * SEQ * HD];
__device__ __align__(16) __nv_bfloat16 g_vl[NH * SEQ * HD];
__device__ __align__(16) __nv_bfloat16 g_ch[SEQ * HID];
__device__ __align__(16) __nv_bfloat16 g_cl[SEQ * HID];

// ---------------- helpers ----------------
__device__ __forceinline__ float ex2f(float x) {
    float r;
    asm("ex2.approx.f32 %0, %1;" : "=f"(r) : "f"(x));
    return r;
}
__device__ __forceinline__ uint32_t packhi2(float a, float b) {
    uint32_t d;
    asm("prmt.b32 %0, %1, %2, 0x7632;"
        : "=r"(d) : "r"(__float_as_uint(a)), "r"(__float_as_uint(b)));
    return d;
}
__device__ __forceinline__ float truncbf(float f) {
    return __uint_as_float(__float_as_uint(f) & 0xffff0000u);
}
// RN bf16 pair: lo16 = bf16rn(a), hi16 = bf16rn(b)
__device__ __forceinline__ uint32_t packlo2(float a, float b) {
    uint32_t d;
    asm("cvt.rn.bf16x2.f32 %0, %2, %1;" : "=r"(d) : "f"(a), "f"(b));
    return d;
}
__device__ __forceinline__ uint32_t smem_u32(const void* p) {
    uint32_t a;
    asm("{ .reg .u64 t; cvta.to.shared.u64 t, %1; cvt.u32.u64 %0, t; }"
        : "=r"(a) : "l"(p));
    return a;
}
__device__ __forceinline__ void ldsm4(uint32_t r[4], uint32_t addr) {
    asm volatile("ldmatrix.sync.aligned.m8n8.x4.shared.b16 {%0,%1,%2,%3}, [%4];"
                 : "=r"(r[0]), "=r"(r[1]), "=r"(r[2]), "=r"(r[3]) : "r"(addr));
}
__device__ __forceinline__ void ldsm4t(uint32_t r[4], uint32_t addr) {
    asm volatile("ldmatrix.sync.aligned.m8n8.x4.trans.shared.b16 {%0,%1,%2,%3}, [%4];"
                 : "=r"(r[0]), "=r"(r[1]), "=r"(r[2]), "=r"(r[3]) : "r"(addr));
}
__device__ __forceinline__ void mma_bf16(float d[4], const uint32_t a[4],
                                         const uint32_t b[2]) {
    asm volatile(
        "mma.sync.aligned.m16n8k16.row.col.f32.bf16.bf16.f32 "
        "{%0,%1,%2,%3}, {%4,%5,%6,%7}, {%8,%9}, {%0,%1,%2,%3};"
        : "+f"(d[0]), "+f"(d[1]), "+f"(d[2]), "+f"(d[3])
        : "r"(a[0]), "r"(a[1]), "r"(a[2]), "r"(a[3]), "r"(b[0]), "r"(b[1]));
}
__device__ __forceinline__ void cp16(uint32_t dst, const void* src) {
    asm volatile("cp.async.cg.shared.global [%0], [%1], 16;"
                 :: "r"(dst), "l"(src) : "memory");
}
#define CP_COMMIT() asm volatile("cp.async.commit_group;" ::: "memory")
template <int N>
__device__ __forceinline__ void cp_wait() {
    asm volatile("cp.async.wait_group %0;" :: "n"(N) : "memory");
}

// =====================================================================
//      split kernel: fp32 -> bf16 hi/lo (truncation split)
// =====================================================================
__global__ void __launch_bounds__(256) split_kernel(
    const float* __restrict__ X,
    const float* __restrict__ qw, const float* __restrict__ kw,
    const float* __restrict__ vw, const float* __restrict__ ow) {
    const int y = blockIdx.y;
    const float* src;
    __nv_bfloat16 *dh, *dl;
    int n;
    if (y == 0)      { src = X;  dh = g_xh;           dl = g_xl;           n = SEQ * HID; }
    else if (y == 1) { src = qw; dh = g_wh;           dl = g_wl;           n = WSZ; }
    else if (y == 2) { src = kw; dh = g_wh + WSZ;     dl = g_wl + WSZ;     n = WSZ; }
    else if (y == 3) { src = vw; dh = g_wh + 2 * WSZ; dl = g_wl + 2 * WSZ; n = WSZ; }
    else             { src = ow; dh = g_wh + 3 * WSZ; dl = g_wl + 3 * WSZ; n = WSZ; }

    int i = (blockIdx.x * 256 + threadIdx.x) * 4;
    if (i < n) {
        float4 v = *(const float4*)(src + i);
        *(uint2*)&dh[i] = make_uint2(packhi2(v.x, v.y), packhi2(v.z, v.w));
        *(uint2*)&dl[i] = make_uint2(
            packlo2(v.x - truncbf(v.x), v.y - truncbf(v.y)),
            packlo2(v.z - truncbf(v.z), v.w - truncbf(v.w)));
    }
}

// =====================================================================
//   tensor-core GEMM core: C(128x64) = A(M,768) * B(N,768)^T
//   bf16 hi/lo 3-term, KC=32, 2-stage cp.async, 3 CTAs/SM  (unchanged)
// =====================================================================
#define GK HID
#define NCHUNK (GK / 32)        // 24
#define GST 80
#define GA_LO 10240
#define GB_HI 20480
#define GB_LO 25600
#define G_STG 30720
#define G_SMEM (2 * G_STG)      // 61440 -> 3 CTAs/SM

__device__ __forceinline__ void tgemm_core(
    const __nv_bfloat16* __restrict__ Ah, const __nv_bfloat16* __restrict__ Al,
    const __nv_bfloat16* __restrict__ Bh, const __nv_bfloat16* __restrict__ Bl,
    int rowBase, int colBase, uint32_t smb, float acc[2][4][4]) {
    const int tid = threadIdx.x;
    const int wid = tid >> 5, lane = tid & 31;
    const int mBase = (wid & 3) * 32, nBase = (wid >> 2) * 32;
    const int sel = lane >> 3, l7 = lane & 7;
    const int kKey = ((sel & 2) ? 8 : 0) + l7;
    const int kD = (sel & 1) ? 8 : 0;

    const int ar = tid >> 1, ac = tid & 1;
    const int br = tid >> 2, bc = tid & 3;
    const uint32_t aDst = (uint32_t)(ar * GST + ac * 32);
    const uint32_t bDst = (uint32_t)(GB_HI + br * GST + bc * 16);
    const size_t aOff = (size_t)(rowBase + ar) * GK + ac * 16;
    const size_t bOff = (size_t)(colBase + br) * GK + bc * 8;

    auto issue_chunk = [&](int kc, int stg) {
        uint32_t s = smb + stg * G_STG;
        size_t ka = aOff + (size_t)kc * 32;
        size_t kb = bOff + (size_t)kc * 32;
        cp16(s + aDst,              Ah + ka);
        cp16(s + aDst + 16,         Ah + ka + 8);
        cp16(s + aDst + GA_LO,      Al + ka);
        cp16(s + aDst + GA_LO + 16, Al + ka + 8);
        cp16(s + bDst,              Bh + kb);
        cp16(s + bDst + (GB_LO - GB_HI), Bl + kb);
        CP_COMMIT();
    };

    issue_chunk(0, 0);

    for (int kc = 0; kc < NCHUNK; kc++) {
        __syncthreads();
        if (kc + 1 < NCHUNK) issue_chunk(kc + 1, (kc + 1) & 1);
        if (kc + 1 < NCHUNK) cp_wait<1>(); else cp_wait<0>();
        __syncthreads();

        const uint32_t base = smb + (kc & 1) * G_STG;
        #pragma unroll
        for (int k2 = 0; k2 < 2; k2++) {
            const uint32_t colb = (uint32_t)(k2 * 32 + kD * 2);
            uint32_t ah[2][4], alw[2][4], bh[2][4], bl[2][4];
            #pragma unroll
            for (int mt = 0; mt < 2; mt++) {
                uint32_t addr = base + (uint32_t)((mBase + mt * 16 + kKey) * GST) + colb;
                uint32_t t[4];
                ldsm4(t, addr);
                ah[mt][0] = t[0]; ah[mt][1] = t[2]; ah[mt][2] = t[1]; ah[mt][3] = t[3];
                ldsm4(t, addr + GA_LO);
                alw[mt][0] = t[0]; alw[mt][1] = t[2]; alw[mt][2] = t[1]; alw[mt][3] = t[3];
            }
            #pragma unroll
            for (int np = 0; np < 2; np++) {
                uint32_t addr = base + GB_HI +
                                (uint32_t)((nBase + np * 16 + kKey) * GST) + colb;
                ldsm4(bh[np], addr);
                ldsm4(bl[np], addr + (GB_LO - GB_HI));
            }
            #pragma unroll
            for (int mt = 0; mt < 2; mt++)
                #pragma unroll
                for (int np = 0; np < 2; np++)
                    #pragma unroll
                    for (int h = 0; h < 2; h++) {
                        int nt = np * 2 + h;
                        mma_bf16(acc[mt][nt], ah[mt],  &bh[np][2 * h]);
                        mma_bf16(acc[mt][nt], ah[mt],  &bl[np][2 * h]);
                        mma_bf16(acc[mt][nt], alw[mt], &bh[np][2 * h]);
                    }
        }
    }
}

// ---------------- QKV: X * W^T + b, head-major bf16 out ----------------
// z==0 (Q): hi=trunc + lo residual; z==1 (K): single RN bf16; z==2 (V): hi+lo
__global__ void __launch_bounds__(256, 3) qkv_tc_kernel(
    const float* __restrict__ qb, const float* __restrict__ kb,
    const float* __restrict__ vb) {
    extern __shared__ char sm[];
    const uint32_t smb = smem_u32(sm);
    const int z = blockIdx.z;
    const __nv_bfloat16* Bh = g_wh + (size_t)z * WSZ;
    const __nv_bfloat16* Bl = g_wl + (size_t)z * WSZ;
    const float* bias = (z == 0) ? qb : (z == 1) ? kb : vb;
    __nv_bfloat16* outh = (z == 0) ? g_qh : (z == 1) ? g_kh : g_vh;
    __nv_bfloat16* outl = (z == 0) ? g_ql : g_vl;   // unused for z==1
    const float sc = (z == 0) ? QSCALE : 1.0f;

    const int rowBase = blockIdx.y * 128, colBase = blockIdx.x * 64;

    float acc[2][4][4];
    #pragma unroll
    for (int a = 0; a < 2; a++)
        #pragma unroll
        for (int b = 0; b < 4; b++)
            #pragma unroll
            for (int c = 0; c < 4; c++) acc[a][b][c] = 0.0f;

    tgemm_core(g_xh, g_xl, Bh, Bl, rowBase, colBase, smb, acc);

    const int tid = threadIdx.x, wid = tid >> 5, lane = tid & 31;
    const int g = lane >> 2, tig = lane & 3;
    const int mBase = (wid & 3) * 32, nBase = (wid >> 2) * 32;
    const int h = colBase >> 6;

    #pragma unroll
    for (int mt = 0; mt < 2; mt++) {
        int m0 = rowBase + mBase + mt * 16 + g;
        #pragma unroll
        for (int nt = 0; nt < 4; nt++) {
            int col = colBase + nBase + nt * 8 + 2 * tig;
            int d = col & 63;
            float b0 = bias[col], b1 = bias[col + 1];
            size_t i0 = (size_t)(h * SEQ + m0) * HD + d;
            size_t i1 = i0 + (size_t)8 * HD;
            float f0 = (acc[mt][nt][0] + b0) * sc;
            float f1 = (acc[mt][nt][1] + b1) * sc;
            float f2 = (acc[mt][nt][2] + b0) * sc;
            float f3 = (acc[mt][nt][3] + b1) * sc;
            if (z == 1) {
                *(uint32_t*)&outh[i0] = packlo2(f0, f1);
                *(uint32_t*)&outh[i1] = packlo2(f2, f3);
            } else {
                *(uint32_t*)&outh[i0] = packhi2(f0, f1);
                *(uint32_t*)&outl[i0] = packlo2(f0 - truncbf(f0), f1 - truncbf(f1));
                *(uint32_t*)&outh[i1] = packhi2(f2, f3);
                *(uint32_t*)&outl[i1] = packlo2(f2 - truncbf(f2), f3 - truncbf(f3));
            }
        }
    }
}

// ---------------- out proj: ctx * ow^T + ob -> fp32 --------------------
__global__ void __launch_bounds__(256, 3) proj_tc_kernel(
    const float* __restrict__ ob, float* __restrict__ outp) {
    extern __shared__ char sm[];
    const uint32_t smb = smem_u32(sm);
    const int rowBase = blockIdx.y * 128, colBase = blockIdx.x * 64;

    float acc[2][4][4];
    #pragma unroll
    for (int a = 0; a < 2; a++)
        #pragma unroll
        for (int b = 0; b < 4; b++)
            #pragma unroll
            for (int c = 0; c < 4; c++) acc[a][b][c] = 0.0f;

    tgemm_core(g_ch, g_cl, g_wh + 3 * (size_t)WSZ, g_wl + 3 * (size_t)WSZ,
               rowBase, colBase, smb, acc);

    const int tid = threadIdx.x, wid = tid >> 5, lane = tid & 31;
    const int g = lane >> 2, tig = lane & 3;
    const int mBase = (wid & 3) * 32, nBase = (wid >> 2) * 32;

    #pragma unroll
    for (int mt = 0; mt < 2; mt++) {
        int m0 = rowBase + mBase + mt * 16 + g;
        #pragma unroll
        for (int nt = 0; nt < 4; nt++) {
            int col = colBase + nBase + nt * 8 + 2 * tig;
            float b0 = ob[col], b1 = ob[col + 1];
            *(float2*)&outp[(size_t)m0 * HID + col] =
                make_float2(acc[mt][nt][0] + b0, acc[mt][nt][1] + b1);
            *(float2*)&outp[(size_t)(m0 + 8) * HID + col] =
                make_float2(acc[mt][nt][2] + b0, acc[mt][nt][3] + b1);
        }
    }
}

// =====================================================================
//   flash attention: 3-stage cp.async ring, ONE barrier per tile,
//   Q-lo in smem (persistent), mask staged per tile in the ring (fp32),
//   S = 2-term, PV = 3-term, 2 CTAs/SM, MUFU ex2 softmax.
// =====================================================================
#define KV_STR 72
#define ARR_B  (64 * KV_STR * 2)            // 9216
#define MSKT_B 256                          // 64 fp32 mask values per tile
#define BUF_B  (3 * ARR_B + MSKT_B)         // 27904 per stage (Khi,Vhi,Vlo,mask)
#define QLO_OFF (3 * BUF_B)                 // 83712
#define QLO_B  (128 * KV_STR * 2)           // 18432
#define FL_SMEM (QLO_OFF + QLO_B)           // 102144 -> 2 CTAs/SM

__global__ void __launch_bounds__(256, 2) flash_mma_kernel(const float* __restrict__ mask) {
    extern __shared__ char sm[];
    const uint32_t smb = smem_u32(sm);

    const int tid  = threadIdx.x;
    const int wid  = tid >> 5;
    const int lane = tid & 31;
    const int g    = lane >> 2;
    const int tig  = lane & 3;

    const int head  = blockIdx.y;
    const int qBase = blockIdx.x * 128;

    const int sel = lane >> 3, l7 = lane & 7;
    const int kKey = ((sel & 2) ? 8 : 0) + l7, kD = (sel & 1) ? 8 : 0;
    const int vKey = ((sel & 1) ? 8 : 0) + l7, vD = (sel & 2) ? 8 : 0;

    const int cpRow  = tid >> 2;
    const int cpChk  = tid & 3;
    const size_t gTileBase = (size_t)head * SEQ * HD;
    const uint32_t cpDstOff = (uint32_t)(cpRow * (KV_STR * 2) + cpChk * 32);

    auto issue_tile = [&](int t, int buf) {
        size_t gidx = gTileBase + (size_t)(t * 64 + cpRow) * HD + cpChk * 16;
        uint32_t d0 = smb + buf * BUF_B + cpDstOff;
        cp16(d0,                  g_kh + gidx);
        cp16(d0 + 16,             g_kh + gidx + 8);
        cp16(d0 + ARR_B,          g_vh + gidx);
        cp16(d0 + ARR_B + 16,     g_vh + gidx + 8);
        cp16(d0 + 2 * ARR_B,      g_vl + gidx);
        cp16(d0 + 2 * ARR_B + 16, g_vl + gidx + 8);
        if (tid < 16)
            cp16(smb + buf * BUF_B + 3 * ARR_B + tid * 16, mask + t * 64 + tid * 4);
        CP_COMMIT();
    };

    // ---- Q-lo -> smem, committed together with tile 0's group ----
    {
        int row = tid >> 1, half = tid & 1;
        const __nv_bfloat16* src =
            g_ql + ((size_t)head * SEQ + qBase + row) * HD + half * 32;
        uint32_t dst = smb + QLO_OFF + (uint32_t)(row * (KV_STR * 2) + half * 64);
        cp16(dst,      src);
        cp16(dst + 16, src + 8);
        cp16(dst + 32, src + 16);
        cp16(dst + 48, src + 24);
    }
    issue_tile(0, 0);      // group 0 = {Q-lo, tile0}
    issue_tile(1, 1);      // group 1 = {tile1}

    // ---- Q-hi fragments from gmem (registers) ----
    uint32_t qfh[4][4];
    {
        const uint32_t* qh32 = (const uint32_t*)g_qh + (size_t)head * SEQ * 32;
        const int r0 = qBase + wid * 16 + g;
        #pragma unroll
        for (int ks = 0; ks < 4; ks++) {
            int c0 = ks * 8 + tig;
            int c1 = c0 + 4;
            qfh[ks][0] = qh32[r0 * 32 + c0];
            qfh[ks][1] = qh32[(r0 + 8) * 32 + c0];
            qfh[ks][2] = qh32[r0 * 32 + c1];
            qfh[ks][3] = qh32[(r0 + 8) * 32 + c1];
        }
    }

    float o[8][4];
    #pragma unroll
    for (int j = 0; j < 8; j++)
        #pragma unroll
        for (int r = 0; r < 4; r++) o[j][r] = 0.0f;
    float l0 = 0.0f, l1 = 0.0f;

    const uint32_t qloBase = smb + QLO_OFF +
        (uint32_t)(((wid * 16 + kKey) * KV_STR + kD) * 2);

    for (int t = 0; t < 64; t++) {
        __syncthreads();                   // all warps done with tile t-1
        if (t + 2 < 64) issue_tile(t + 2, (t + 2) % 3);  // overwrites stage of t-1
        if (t + 2 < 64)      cp_wait<2>(); // group t retired -> tile t (+Qlo) landed
        else if (t + 1 < 64) cp_wait<1>();
        else                 cp_wait<0>();

        const uint32_t kb = smb + (t % 3) * BUF_B;
        const uint32_t sKhi = kb;
        const uint32_t sVhi = kb + ARR_B, sVlo = kb + 2 * ARR_B;
        const float* mskp = (const float*)(sm + (t % 3) * BUF_B + 3 * ARR_B);

        float sacc[8][4];
        #pragma unroll
        for (int j = 0; j < 8; j++)
            #pragma unroll
            for (int r = 0; r < 4; r++) sacc[j][r] = 0.0f;

        #pragma unroll
        for (int ks = 0; ks < 4; ks++) {
            uint32_t tq[4], qlo[4];
            ldsm4(tq, qloBase + (uint32_t)(32 * ks));
            qlo[0] = tq[0]; qlo[1] = tq[2]; qlo[2] = tq[1]; qlo[3] = tq[3];
            #pragma unroll
            for (int jp = 0; jp < 4; jp++) {
                uint32_t boff = (uint32_t)(((16 * jp + kKey) * KV_STR + 16 * ks + kD) * 2);
                uint32_t kh[4];
                ldsm4(kh, sKhi + boff);
                mma_bf16(sacc[2 * jp],     qfh[ks], &kh[0]);
                mma_bf16(sacc[2 * jp],     qlo,     &kh[0]);
                mma_bf16(sacc[2 * jp + 1], qfh[ks], &kh[2]);
                mma_bf16(sacc[2 * jp + 1], qlo,     &kh[2]);
            }
        }

        // softmax: MUFU ex2 + truncation split packing; mask from ring stage
        uint32_t pfh[4][4], pfl[4][4];
        #pragma unroll
        for (int j = 0; j < 8; j++) {
            float2 m2 = *(const float2*)&mskp[8 * j + 2 * tig];
            m2.x *= LOG2E; m2.y *= LOG2E;
            float p0 = ex2f(sacc[j][0] + m2.x);
            float p1 = ex2f(sacc[j][1] + m2.y);
            float p2 = ex2f(sacc[j][2] + m2.x);
            float p3 = ex2f(sacc[j][3] + m2.y);
            l0 += p0 + p1;
            l1 += p2 + p3;
            int ks = j >> 1, odd = (j & 1) ? 2 : 0;
            pfh[ks][odd]     = packhi2(p0, p1);
            pfh[ks][odd + 1] = packhi2(p2, p3);
            pfl[ks][odd]     = packlo2(p0 - truncbf(p0), p1 - truncbf(p1));
            pfl[ks][odd + 1] = packlo2(p2 - truncbf(p2), p3 - truncbf(p3));
        }

        #pragma unroll
        for (int ks = 0; ks < 4; ks++) {
            #pragma unroll
            for (int jd = 0; jd < 4; jd++) {
                uint32_t boff = (uint32_t)(((16 * ks + vKey) * KV_STR + 16 * jd + vD) * 2);
                uint32_t vh[4], vl[4];
                ldsm4t(vh, sVhi + boff);
                ldsm4t(vl, sVlo + boff);
                mma_bf16(o[2 * jd],     pfh[ks], &vh[0]);
                mma_bf16(o[2 * jd],     pfh[ks], &vl[0]);
                mma_bf16(o[2 * jd],     pfl[ks], &vh[0]);
                mma_bf16(o[2 * jd + 1], pfh[ks], &vh[2]);
                mma_bf16(o[2 * jd + 1], pfh[ks], &vl[2]);
                mma_bf16(o[2 * jd + 1], pfl[ks], &vh[2]);
            }
        }
    }

    l0 += __shfl_xor_sync(0xffffffffu, l0, 1);
    l0 += __shfl_xor_sync(0xffffffffu, l0, 2);
    l1 += __shfl_xor_sync(0xffffffffu, l1, 1);
    l1 += __shfl_xor_sync(0xffffffffu, l1, 2);
    float inv0 = 1.0f / l0, inv1 = 1.0f / l1;

    const int r0 = qBase + wid * 16 + g;
    #pragma unroll
    for (int j = 0; j < 8; j++) {
        int c = 8 * j + 2 * tig;
        size_t i0 = (size_t)r0 * HID + head * HD + c;
        size_t i1 = (size_t)(r0 + 8) * HID + head * HD + c;
        float a0 = o[j][0] * inv0, a1 = o[j][1] * inv0;
        float a2 = o[j][2] * inv1, a3 = o[j][3] * inv1;
        *(uint32_t*)&g_ch[i0] = packhi2(a0, a1);
        *(uint32_t*)&g_cl[i0] = packlo2(a0 - truncbf(a0), a1 - truncbf(a1));
        *(uint32_t*)&g_ch[i1] = packhi2(a2, a3);
        *(uint32_t*)&g_cl[i1] = packlo2(a2 - truncbf(a2), a3 - truncbf(a3));
    }
}

// ---------------- launch ------------------------------------------------
extern "C" void kernel_launch(void* const* d_in, const int* in_sizes, int n_in,
                              void* d_out, int out_size) {
    const float* X    = (const float*)d_in[0];
    const float* mask = (const float*)d_in[1];
    const float* qw   = (const float*)d_in[2];
    const float* qb   = (const float*)d_in[3];
    const float* kw   = (const float*)d_in[4];
    const float* kb   = (const float*)d_in[5];
    const float* vw   = (const float*)d_in[6];
    const float* vb   = (const float*)d_in[7];
    const float* ow   = (const float*)d_in[8];
    const float* ob   = (const float*)d_in[9];
    float* out = (float*)d_out;

    cudaFuncSetAttribute(flash_mma_kernel,
                         cudaFuncAttributeMaxDynamicSharedMemorySize, FL_SMEM);
    cudaFuncSetAttribute(qkv_tc_kernel,
                         cudaFuncAttributeMaxDynamicSharedMemorySize, G_SMEM);
    cudaFuncSetAttribute(proj_tc_kernel,
                         cudaFuncAttributeMaxDynamicSharedMemorySize, G_SMEM);

    split_kernel<<<dim3(SEQ * HID / 1024, 5), 256>>>(X, qw, kw, vw, ow);

    qkv_tc_kernel<<<dim3(HID / 64, SEQ / 128, 3), 256, G_SMEM>>>(qb, kb, vb);

    flash_mma_kernel<<<dim3(SEQ / 128, NH), 256, FL_SMEM>>>(mask);

    proj_tc_kernel<<<dim3(HID / 64, SEQ / 128), 256, G_SMEM>>>(ob, out);
}

// round 15
// speedup vs baseline: 1.2186x; 1.0038x over previous
#include <cuda_runtime.h>
#include <cuda_bf16.h>
#include <cstdint>

#define SEQ 4096
#define HID 768
#define NH  12
#define HD  64
#define WSZ (HID * HID)
#define LOG2E 1.4426950408889634f
#define QSCALE (0.125f * LOG2E)

// ---------------- device scratch ----------------
__device__ __align__(16) __nv_bfloat16 g_xh[SEQ * HID];
__device__ __align__(16) __nv_bfloat16 g_xl[SEQ * HID];
__device__ __align__(16) __nv_bfloat16 g_wh[4 * WSZ];   // qw,kw,vw,ow
__device__ __align__(16) __nv_bfloat16 g_wl[4 * WSZ];
__device__ __align__(16) __nv_bfloat16 g_qh[NH * SEQ * HD];
__device__ __align__(16) __nv_bfloat16 g_ql[NH * SEQ * HD];
__device__ __align__(16) __nv_bfloat16 g_kh[NH * SEQ * HD];   // RN bf16 (no lo)
__device__ __align__(16) __nv_bfloat16 g_vh[NH * SEQ * HD];
__device__ __align__(16) __nv_bfloat16 g_vl[NH * SEQ * HD];
__device__ __align__(16) __nv_bfloat16 g_ch[SEQ * HID];
__device__ __align__(16) __nv_bfloat16 g_cl[SEQ * HID];
// split-KV partials
__device__ __align__(16) float g_op[2 * SEQ * HID];
__device__ __align__(16) float g_lp[2 * NH * SEQ];

// ---------------- helpers ----------------
__device__ __forceinline__ float ex2f(float x) {
    float r;
    asm("ex2.approx.f32 %0, %1;" : "=f"(r) : "f"(x));
    return r;
}
__device__ __forceinline__ uint32_t packhi2(float a, float b) {
    uint32_t d;
    asm("prmt.b32 %0, %1, %2, 0x7632;"
        : "=r"(d) : "r"(__float_as_uint(a)), "r"(__float_as_uint(b)));
    return d;
}
__device__ __forceinline__ float truncbf(float f) {
    return __uint_as_float(__float_as_uint(f) & 0xffff0000u);
}
__device__ __forceinline__ uint32_t packlo2(float a, float b) {
    uint32_t d;
    asm("cvt.rn.bf16x2.f32 %0, %2, %1;" : "=r"(d) : "f"(a), "f"(b));
    return d;
}
__device__ __forceinline__ uint32_t smem_u32(const void* p) {
    uint32_t a;
    asm("{ .reg .u64 t; cvta.to.shared.u64 t, %1; cvt.u32.u64 %0, t; }"
        : "=r"(a) : "l"(p));
    return a;
}
__device__ __forceinline__ void ldsm4(uint32_t r[4], uint32_t addr) {
    asm volatile("ldmatrix.sync.aligned.m8n8.x4.shared.b16 {%0,%1,%2,%3}, [%4];"
                 : "=r"(r[0]), "=r"(r[1]), "=r"(r[2]), "=r"(r[3]) : "r"(addr));
}
__device__ __forceinline__ void ldsm4t(uint32_t r[4], uint32_t addr) {
    asm volatile("ldmatrix.sync.aligned.m8n8.x4.trans.shared.b16 {%0,%1,%2,%3}, [%4];"
                 : "=r"(r[0]), "=r"(r[1]), "=r"(r[2]), "=r"(r[3]) : "r"(addr));
}
__device__ __forceinline__ void mma_bf16(float d[4], const uint32_t a[4],
                                         const uint32_t b[2]) {
    asm volatile(
        "mma.sync.aligned.m16n8k16.row.col.f32.bf16.bf16.f32 "
        "{%0,%1,%2,%3}, {%4,%5,%6,%7}, {%8,%9}, {%0,%1,%2,%3};"
        : "+f"(d[0]), "+f"(d[1]), "+f"(d[2]), "+f"(d[3])
        : "r"(a[0]), "r"(a[1]), "r"(a[2]), "r"(a[3]), "r"(b[0]), "r"(b[1]));
}
__device__ __forceinline__ void cp16(uint32_t dst, const void* src) {
    asm volatile("cp.async.cg.shared.global [%0], [%1], 16;"
                 :: "r"(dst), "l"(src) : "memory");
}
#define CP_COMMIT() asm volatile("cp.async.commit_group;" ::: "memory")
template <int N>
__device__ __forceinline__ void cp_wait() {
    asm volatile("cp.async.wait_group %0;" :: "n"(N) : "memory");
}

// =====================================================================
//      split kernel: fp32 -> bf16 hi/lo (truncation split)
// =====================================================================
__global__ void __launch_bounds__(256) split_kernel(
    const float* __restrict__ X,
    const float* __restrict__ qw, const float* __restrict__ kw,
    const float* __restrict__ vw, const float* __restrict__ ow) {
    const int y = blockIdx.y;
    const float* src;
    __nv_bfloat16 *dh, *dl;
    int n;
    if (y == 0)      { src = X;  dh = g_xh;           dl = g_xl;           n = SEQ * HID; }
    else if (y == 1) { src = qw; dh = g_wh;           dl = g_wl;           n = WSZ; }
    else if (y == 2) { src = kw; dh = g_wh + WSZ;     dl = g_wl + WSZ;     n = WSZ; }
    else if (y == 3) { src = vw; dh = g_wh + 2 * WSZ; dl = g_wl + 2 * WSZ; n = WSZ; }
    else             { src = ow; dh = g_wh + 3 * WSZ; dl = g_wl + 3 * WSZ; n = WSZ; }

    int i = (blockIdx.x * 256 + threadIdx.x) * 4;
    if (i < n) {
        float4 v = *(const float4*)(src + i);
        *(uint2*)&dh[i] = make_uint2(packhi2(v.x, v.y), packhi2(v.z, v.w));
        *(uint2*)&dl[i] = make_uint2(
            packlo2(v.x - truncbf(v.x), v.y - truncbf(v.y)),
            packlo2(v.z - truncbf(v.z), v.w - truncbf(v.w)));
    }
}

// =====================================================================
//   tensor-core GEMM core: C(128x64) = A(M,768) * B(N,768)^T  (unchanged)
// =====================================================================
#define GK HID
#define NCHUNK (GK / 32)        // 24
#define GST 80
#define GA_LO 10240
#define GB_HI 20480
#define GB_LO 25600
#define G_STG 30720
#define G_SMEM (2 * G_STG)      // 61440 -> 3 CTAs/SM

__device__ __forceinline__ void tgemm_core(
    const __nv_bfloat16* __restrict__ Ah, const __nv_bfloat16* __restrict__ Al,
    const __nv_bfloat16* __restrict__ Bh, const __nv_bfloat16* __restrict__ Bl,
    int rowBase, int colBase, uint32_t smb, float acc[2][4][4]) {
    const int tid = threadIdx.x;
    const int wid = tid >> 5, lane = tid & 31;
    const int mBase = (wid & 3) * 32, nBase = (wid >> 2) * 32;
    const int sel = lane >> 3, l7 = lane & 7;
    const int kKey = ((sel & 2) ? 8 : 0) + l7;
    const int kD = (sel & 1) ? 8 : 0;

    const int ar = tid >> 1, ac = tid & 1;
    const int br = tid >> 2, bc = tid & 3;
    const uint32_t aDst = (uint32_t)(ar * GST + ac * 32);
    const uint32_t bDst = (uint32_t)(GB_HI + br * GST + bc * 16);
    const size_t aOff = (size_t)(rowBase + ar) * GK + ac * 16;
    const size_t bOff = (size_t)(colBase + br) * GK + bc * 8;

    auto issue_chunk = [&](int kc, int stg) {
        uint32_t s = smb + stg * G_STG;
        size_t ka = aOff + (size_t)kc * 32;
        size_t kb = bOff + (size_t)kc * 32;
        cp16(s + aDst,              Ah + ka);
        cp16(s + aDst + 16,         Ah + ka + 8);
        cp16(s + aDst + GA_LO,      Al + ka);
        cp16(s + aDst + GA_LO + 16, Al + ka + 8);
        cp16(s + bDst,              Bh + kb);
        cp16(s + bDst + (GB_LO - GB_HI), Bl + kb);
        CP_COMMIT();
    };

    issue_chunk(0, 0);

    for (int kc = 0; kc < NCHUNK; kc++) {
        __syncthreads();
        if (kc + 1 < NCHUNK) issue_chunk(kc + 1, (kc + 1) & 1);
        if (kc + 1 < NCHUNK) cp_wait<1>(); else cp_wait<0>();
        __syncthreads();

        const uint32_t base = smb + (kc & 1) * G_STG;
        #pragma unroll
        for (int k2 = 0; k2 < 2; k2++) {
            const uint32_t colb = (uint32_t)(k2 * 32 + kD * 2);
            uint32_t ah[2][4], alw[2][4], bh[2][4], bl[2][4];
            #pragma unroll
            for (int mt = 0; mt < 2; mt++) {
                uint32_t addr = base + (uint32_t)((mBase + mt * 16 + kKey) * GST) + colb;
                uint32_t t[4];
                ldsm4(t, addr);
                ah[mt][0] = t[0]; ah[mt][1] = t[2]; ah[mt][2] = t[1]; ah[mt][3] = t[3];
                ldsm4(t, addr + GA_LO);
                alw[mt][0] = t[0]; alw[mt][1] = t[2]; alw[mt][2] = t[1]; alw[mt][3] = t[3];
            }
            #pragma unroll
            for (int np = 0; np < 2; np++) {
                uint32_t addr = base + GB_HI +
                                (uint32_t)((nBase + np * 16 + kKey) * GST) + colb;
                ldsm4(bh[np], addr);
                ldsm4(bl[np], addr + (GB_LO - GB_HI));
            }
            #pragma unroll
            for (int mt = 0; mt < 2; mt++)
                #pragma unroll
                for (int np = 0; np < 2; np++)
                    #pragma unroll
                    for (int h = 0; h < 2; h++) {
                        int nt = np * 2 + h;
                        mma_bf16(acc[mt][nt], ah[mt],  &bh[np][2 * h]);
                        mma_bf16(acc[mt][nt], ah[mt],  &bl[np][2 * h]);
                        mma_bf16(acc[mt][nt], alw[mt], &bh[np][2 * h]);
                    }
        }
    }
}

// ---------------- QKV: X * W^T + b, head-major bf16 out ----------------
__global__ void __launch_bounds__(256, 3) qkv_tc_kernel(
    const float* __restrict__ qb, const float* __restrict__ kb,
    const float* __restrict__ vb) {
    extern __shared__ char sm[];
    const uint32_t smb = smem_u32(sm);
    const int z = blockIdx.z;
    const __nv_bfloat16* Bh = g_wh + (size_t)z * WSZ;
    const __nv_bfloat16* Bl = g_wl + (size_t)z * WSZ;
    const float* bias = (z == 0) ? qb : (z == 1) ? kb : vb;
    __nv_bfloat16* outh = (z == 0) ? g_qh : (z == 1) ? g_kh : g_vh;
    __nv_bfloat16* outl = (z == 0) ? g_ql : g_vl;   // unused for z==1
    const float sc = (z == 0) ? QSCALE : 1.0f;

    const int rowBase = blockIdx.y * 128, colBase = blockIdx.x * 64;

    float acc[2][4][4];
    #pragma unroll
    for (int a = 0; a < 2; a++)
        #pragma unroll
        for (int b = 0; b < 4; b++)
            #pragma unroll
            for (int c = 0; c < 4; c++) acc[a][b][c] = 0.0f;

    tgemm_core(g_xh, g_xl, Bh, Bl, rowBase, colBase, smb, acc);

    const int tid = threadIdx.x, wid = tid >> 5, lane = tid & 31;
    const int g = lane >> 2, tig = lane & 3;
    const int mBase = (wid & 3) * 32, nBase = (wid >> 2) * 32;
    const int h = colBase >> 6;

    #pragma unroll
    for (int mt = 0; mt < 2; mt++) {
        int m0 = rowBase + mBase + mt * 16 + g;
        #pragma unroll
        for (int nt = 0; nt < 4; nt++) {
            int col = colBase + nBase + nt * 8 + 2 * tig;
            int d = col & 63;
            float b0 = bias[col], b1 = bias[col + 1];
            size_t i0 = (size_t)(h * SEQ + m0) * HD + d;
            size_t i1 = i0 + (size_t)8 * HD;
            float f0 = (acc[mt][nt][0] + b0) * sc;
            float f1 = (acc[mt][nt][1] + b1) * sc;
            float f2 = (acc[mt][nt][2] + b0) * sc;
            float f3 = (acc[mt][nt][3] + b1) * sc;
            if (z == 1) {
                *(uint32_t*)&outh[i0] = packlo2(f0, f1);
                *(uint32_t*)&outh[i1] = packlo2(f2, f3);
            } else {
                *(uint32_t*)&outh[i0] = packhi2(f0, f1);
                *(uint32_t*)&outl[i0] = packlo2(f0 - truncbf(f0), f1 - truncbf(f1));
                *(uint32_t*)&outh[i1] = packhi2(f2, f3);
                *(uint32_t*)&outl[i1] = packlo2(f2 - truncbf(f2), f3 - truncbf(f3));
            }
        }
    }
}

// ---------------- out proj: ctx * ow^T + ob -> fp32 --------------------
__global__ void __launch_bounds__(256, 3) proj_tc_kernel(
    const float* __restrict__ ob, float* __restrict__ outp) {
    extern __shared__ char sm[];
    const uint32_t smb = smem_u32(sm);
    const int rowBase = blockIdx.y * 128, colBase = blockIdx.x * 64;

    float acc[2][4][4];
    #pragma unroll
    for (int a = 0; a < 2; a++)
        #pragma unroll
        for (int b = 0; b < 4; b++)
            #pragma unroll
            for (int c = 0; c < 4; c++) acc[a][b][c] = 0.0f;

    tgemm_core(g_ch, g_cl, g_wh + 3 * (size_t)WSZ, g_wl + 3 * (size_t)WSZ,
               rowBase, colBase, smb, acc);

    const int tid = threadIdx.x, wid = tid >> 5, lane = tid & 31;
    const int g = lane >> 2, tig = lane & 3;
    const int mBase = (wid & 3) * 32, nBase = (wid >> 2) * 32;

    #pragma unroll
    for (int mt = 0; mt < 2; mt++) {
        int m0 = rowBase + mBase + mt * 16 + g;
        #pragma unroll
        for (int nt = 0; nt < 4; nt++) {
            int col = colBase + nBase + nt * 8 + 2 * tig;
            float b0 = ob[col], b1 = ob[col + 1];
            *(float2*)&outp[(size_t)m0 * HID + col] =
                make_float2(acc[mt][nt][0] + b0, acc[mt][nt][1] + b1);
            *(float2*)&outp[(size_t)(m0 + 8) * HID + col] =
                make_float2(acc[mt][nt][2] + b0, acc[mt][nt][3] + b1);
        }
    }
}

// =====================================================================
//   flash attention, split-KV: blockIdx.z halves process 32 tiles each,
//   writing unnormalized fp32 O + l partials. 3-stage ring, 1 barrier.
// =====================================================================
#define KV_STR 72
#define ARR_B  (64 * KV_STR * 2)            // 9216
#define MSKT_B 256
#define BUF_B  (3 * ARR_B + MSKT_B)         // 27904 per stage
#define QLO_OFF (3 * BUF_B)                 // 83712
#define QLO_B  (128 * KV_STR * 2)           // 18432
#define FL_SMEM (QLO_OFF + QLO_B)           // 102144 -> 2 CTAs/SM
#define NT_HALF 32

__global__ void __launch_bounds__(256, 2) flash_mma_kernel(const float* __restrict__ mask) {
    extern __shared__ char sm[];
    const uint32_t smb = smem_u32(sm);

    const int tid  = threadIdx.x;
    const int wid  = tid >> 5;
    const int lane = tid & 31;
    const int g    = lane >> 2;
    const int tig  = lane & 3;

    const int head  = blockIdx.y;
    const int qBase = blockIdx.x * 128;
    const int z     = blockIdx.z;
    const int t0    = z * NT_HALF;

    const int sel = lane >> 3, l7 = lane & 7;
    const int kKey = ((sel & 2) ? 8 : 0) + l7, kD = (sel & 1) ? 8 : 0;
    const int vKey = ((sel & 1) ? 8 : 0) + l7, vD = (sel & 2) ? 8 : 0;

    const int cpRow  = tid >> 2;
    const int cpChk  = tid & 3;
    const size_t gTileBase = (size_t)head * SEQ * HD;
    const uint32_t cpDstOff = (uint32_t)(cpRow * (KV_STR * 2) + cpChk * 32);

    auto issue_tile = [&](int gt, int buf) {
        size_t gidx = gTileBase + (size_t)(gt * 64 + cpRow) * HD + cpChk * 16;
        uint32_t d0 = smb + buf * BUF_B + cpDstOff;
        cp16(d0,                  g_kh + gidx);
        cp16(d0 + 16,             g_kh + gidx + 8);
        cp16(d0 + ARR_B,          g_vh + gidx);
        cp16(d0 + ARR_B + 16,     g_vh + gidx + 8);
        cp16(d0 + 2 * ARR_B,      g_vl + gidx);
        cp16(d0 + 2 * ARR_B + 16, g_vl + gidx + 8);
        if (tid < 16)
            cp16(smb + buf * BUF_B + 3 * ARR_B + tid * 16, mask + gt * 64 + tid * 4);
        CP_COMMIT();
    };

    // ---- Q-lo -> smem, committed with tile t0's group ----
    {
        int row = tid >> 1, half = tid & 1;
        const __nv_bfloat16* src =
            g_ql + ((size_t)head * SEQ + qBase + row) * HD + half * 32;
        uint32_t dst = smb + QLO_OFF + (uint32_t)(row * (KV_STR * 2) + half * 64);
        cp16(dst,      src);
        cp16(dst + 16, src + 8);
        cp16(dst + 32, src + 16);
        cp16(dst + 48, src + 24);
    }
    issue_tile(t0, 0);
    issue_tile(t0 + 1, 1);

    // ---- Q-hi fragments (registers) ----
    uint32_t qfh[4][4];
    {
        const uint32_t* qh32 = (const uint32_t*)g_qh + (size_t)head * SEQ * 32;
        const int r0 = qBase + wid * 16 + g;
        #pragma unroll
        for (int ks = 0; ks < 4; ks++) {
            int c0 = ks * 8 + tig;
            int c1 = c0 + 4;
            qfh[ks][0] = qh32[r0 * 32 + c0];
            qfh[ks][1] = qh32[(r0 + 8) * 32 + c0];
            qfh[ks][2] = qh32[r0 * 32 + c1];
            qfh[ks][3] = qh32[(r0 + 8) * 32 + c1];
        }
    }

    float o[8][4];
    #pragma unroll
    for (int j = 0; j < 8; j++)
        #pragma unroll
        for (int r = 0; r < 4; r++) o[j][r] = 0.0f;
    float l0 = 0.0f, l1 = 0.0f;

    const uint32_t qloBase = smb + QLO_OFF +
        (uint32_t)(((wid * 16 + kKey) * KV_STR + kD) * 2);

    for (int t = 0; t < NT_HALF; t++) {
        __syncthreads();
        if (t + 2 < NT_HALF) issue_tile(t0 + t + 2, (t + 2) % 3);
        if (t + 2 < NT_HALF)      cp_wait<2>();
        else if (t + 1 < NT_HALF) cp_wait<1>();
        else                      cp_wait<0>();

        const uint32_t kb = smb + (t % 3) * BUF_B;
        const uint32_t sKhi = kb;
        const uint32_t sVhi = kb + ARR_B, sVlo = kb + 2 * ARR_B;
        const float* mskp = (const float*)(sm + (t % 3) * BUF_B + 3 * ARR_B);

        float sacc[8][4];
        #pragma unroll
        for (int j = 0; j < 8; j++)
            #pragma unroll
            for (int r = 0; r < 4; r++) sacc[j][r] = 0.0f;

        #pragma unroll
        for (int ks = 0; ks < 4; ks++) {
            uint32_t tq[4], qlo[4];
            ldsm4(tq, qloBase + (uint32_t)(32 * ks));
            qlo[0] = tq[0]; qlo[1] = tq[2]; qlo[2] = tq[1]; qlo[3] = tq[3];
            #pragma unroll
            for (int jp = 0; jp < 4; jp++) {
                uint32_t boff = (uint32_t)(((16 * jp + kKey) * KV_STR + 16 * ks + kD) * 2);
                uint32_t kh[4];
                ldsm4(kh, sKhi + boff);
                mma_bf16(sacc[2 * jp],     qfh[ks], &kh[0]);
                mma_bf16(sacc[2 * jp],     qlo,     &kh[0]);
                mma_bf16(sacc[2 * jp + 1], qfh[ks], &kh[2]);
                mma_bf16(sacc[2 * jp + 1], qlo,     &kh[2]);
            }
        }

        uint32_t pfh[4][4], pfl[4][4];
        #pragma unroll
        for (int j = 0; j < 8; j++) {
            float2 m2 = *(const float2*)&mskp[8 * j + 2 * tig];
            m2.x *= LOG2E; m2.y *= LOG2E;
            float p0 = ex2f(sacc[j][0] + m2.x);
            float p1 = ex2f(sacc[j][1] + m2.y);
            float p2 = ex2f(sacc[j][2] + m2.x);
            float p3 = ex2f(sacc[j][3] + m2.y);
            l0 += p0 + p1;
            l1 += p2 + p3;
            int ks = j >> 1, odd = (j & 1) ? 2 : 0;
            pfh[ks][odd]     = packhi2(p0, p1);
            pfh[ks][odd + 1] = packhi2(p2, p3);
            pfl[ks][odd]     = packlo2(p0 - truncbf(p0), p1 - truncbf(p1));
            pfl[ks][odd + 1] = packlo2(p2 - truncbf(p2), p3 - truncbf(p3));
        }

        #pragma unroll
        for (int ks = 0; ks < 4; ks++) {
            #pragma unroll
            for (int jd = 0; jd < 4; jd++) {
                uint32_t boff = (uint32_t)(((16 * ks + vKey) * KV_STR + 16 * jd + vD) * 2);
                uint32_t vh[4], vl[4];
                ldsm4t(vh, sVhi + boff);
                ldsm4t(vl, sVlo + boff);
                mma_bf16(o[2 * jd],     pfh[ks], &vh[0]);
                mma_bf16(o[2 * jd],     pfh[ks], &vl[0]);
                mma_bf16(o[2 * jd],     pfl[ks], &vh[0]);
                mma_bf16(o[2 * jd + 1], pfh[ks], &vh[2]);
                mma_bf16(o[2 * jd + 1], pfh[ks], &vl[2]);
                mma_bf16(o[2 * jd + 1], pfl[ks], &vh[2]);
            }
        }
    }

    l0 += __shfl_xor_sync(0xffffffffu, l0, 1);
    l0 += __shfl_xor_sync(0xffffffffu, l0, 2);
    l1 += __shfl_xor_sync(0xffffffffu, l1, 1);
    l1 += __shfl_xor_sync(0xffffffffu, l1, 2);

    // ---- write unnormalized partials ----
    const int r0 = qBase + wid * 16 + g;
    if (tig == 0) {
        g_lp[(z * NH + head) * SEQ + r0]     = l0;
        g_lp[(z * NH + head) * SEQ + r0 + 8] = l1;
    }
    float* op = g_op + (size_t)z * SEQ * HID;
    #pragma unroll
    for (int j = 0; j < 8; j++) {
        int c = 8 * j + 2 * tig;
        *(float2*)&op[(size_t)r0 * HID + head * HD + c] =
            make_float2(o[j][0], o[j][1]);
        *(float2*)&op[(size_t)(r0 + 8) * HID + head * HD + c] =
            make_float2(o[j][2], o[j][3]);
    }
}

// ---------------- combine: (O0+O1)/(l0+l1) -> bf16 hi/lo ctx ----------
__global__ void __launch_bounds__(256) combine_kernel() {
    int i = (blockIdx.x * 256 + threadIdx.x) * 4;
    int row = i / HID;
    int col = i % HID;
    int head = col >> 6;
    float l = g_lp[head * SEQ + row] + g_lp[(NH + head) * SEQ + row];
    float inv = 1.0f / l;
    float4 o0 = *(const float4*)&g_op[i];
    float4 o1 = *(const float4*)&g_op[SEQ * HID + i];
    float a0 = (o0.x + o1.x) * inv;
    float a1 = (o0.y + o1.y) * inv;
    float a2 = (o0.z + o1.z) * inv;
    float a3 = (o0.w + o1.w) * inv;
    *(uint2*)&g_ch[i] = make_uint2(packhi2(a0, a1), packhi2(a2, a3));
    *(uint2*)&g_cl[i] = make_uint2(
        packlo2(a0 - truncbf(a0), a1 - truncbf(a1)),
        packlo2(a2 - truncbf(a2), a3 - truncbf(a3)));
}

// ---------------- launch ------------------------------------------------
extern "C" void kernel_launch(void* const* d_in, const int* in_sizes, int n_in,
                              void* d_out, int out_size) {
    const float* X    = (const float*)d_in[0];
    const float* mask = (const float*)d_in[1];
    const float* qw   = (const float*)d_in[2];
    const float* qb   = (const float*)d_in[3];
    const float* kw   = (const float*)d_in[4];
    const float* kb   = (const float*)d_in[5];
    const float* vw   = (const float*)d_in[6];
    const float* vb   = (const float*)d_in[7];
    const float* ow   = (const float*)d_in[8];
    const float* ob   = (const float*)d_in[9];
    float* out = (float*)d_out;

    cudaFuncSetAttribute(flash_mma_kernel,
                         cudaFuncAttributeMaxDynamicSharedMemorySize, FL_SMEM);
    cudaFuncSetAttribute(qkv_tc_kernel,
                         cudaFuncAttributeMaxDynamicSharedMemorySize, G_SMEM);
    cudaFuncSetAttribute(proj_tc_kernel,
                         cudaFuncAttributeMaxDynamicSharedMemorySize, G_SMEM);

    split_kernel<<<dim3(SEQ * HID / 1024, 5), 256>>>(X, qw, kw, vw, ow);

    qkv_tc_kernel<<<dim3(HID / 64, SEQ / 128, 3), 256, G_SMEM>>>(qb, kb, vb);

    flash_mma_kernel<<<dim3(SEQ / 128, NH, 2), 256, FL_SMEM>>>(mask);

    combine_kernel<<<SEQ * HID / 1024, 256>>>();

    proj_tc_kernel<<<dim3(HID / 64, SEQ / 128), 256, G_SMEM>>>(ob, out);
}